// round 11
// baseline (speedup 1.0000x reference)
#include <cuda_runtime.h>
#include <cuda_bf16.h>
#include <math.h>
#include <stdint.h>

// Problem constants
#define B_SZ 4
#define SEQ 2048
#define DM 1024
#define NHEAD 16
#define HD 64
#define DFF 4096
#define M_ROWS (B_SZ * SEQ)   // 8192

typedef __nv_bfloat16 bf16;

// ---------------------------------------------------------------------------
// Scratch buffers
// ---------------------------------------------------------------------------
__device__ float g_q[M_ROWS * DM];
__device__ float g_k[M_ROWS * DM];
__device__ float g_v[M_ROWS * DM];
__device__ float g_x1[M_ROWS * DM];
__device__ float g_gate[M_ROWS * DFF];

__device__ bf16 g_xnh[M_ROWS * DM],  g_xnl[M_ROWS * DM];
__device__ bf16 g_aoh[M_ROWS * DM],  g_aol[M_ROWS * DM];
__device__ bf16 g_hh[M_ROWS * DFF],  g_hl[M_ROWS * DFF];

__device__ bf16 g_wqh[DM * DM],   g_wql[DM * DM];
__device__ bf16 g_wkh[DM * DM],   g_wkl[DM * DM];
__device__ bf16 g_wvh[DM * DM],   g_wvl[DM * DM];
__device__ bf16 g_woh[DM * DM],   g_wol[DM * DM];
__device__ bf16 g_uph[DFF * DM],  g_upl[DFF * DM];
__device__ bf16 g_gwh[DFF * DM],  g_gwl[DFF * DM];
__device__ bf16 g_dwh[DM * DFF],  g_dwl[DM * DFF];

__device__ __forceinline__ void split1(float r, bf16* hi, bf16* lo, size_t off) {
    bf16 h = __float2bfloat16(r);
    hi[off] = h;
    lo[off] = __float2bfloat16(r - __bfloat162float(h));
}

__device__ __forceinline__ void split_pack(float f0, float f1,
                                           unsigned& h, unsigned& l) {
    bf16 h0 = __float2bfloat16(f0), h1 = __float2bfloat16(f1);
    unsigned short u0 = *(unsigned short*)&h0, u1 = *(unsigned short*)&h1;
    h = ((unsigned)u1 << 16) | u0;
    bf16 l0 = __float2bfloat16(f0 - __bfloat162float(h0));
    bf16 l1 = __float2bfloat16(f1 - __bfloat162float(h1));
    unsigned short v0 = *(unsigned short*)&l0, v1 = *(unsigned short*)&l1;
    l = ((unsigned)v1 << 16) | v0;
}

// ---------------------------------------------------------------------------
// Elementwise kernels
// ---------------------------------------------------------------------------
__global__ __launch_bounds__(256)
void split_kernel(const float* __restrict__ src, bf16* __restrict__ hi,
                  bf16* __restrict__ lo) {
    size_t i = ((size_t)blockIdx.x * 256 + threadIdx.x) * 4;
    float4 v = *(const float4*)(src + i);
    split1(v.x, hi, lo, i + 0);
    split1(v.y, hi, lo, i + 1);
    split1(v.z, hi, lo, i + 2);
    split1(v.w, hi, lo, i + 3);
}

__global__ __launch_bounds__(256)
void rmsnorm_split_kernel(const float* __restrict__ x,
                          const float* __restrict__ w,
                          bf16* __restrict__ hi, bf16* __restrict__ lo) {
    int row = blockIdx.x;
    int tid = threadIdx.x;
    const float* xr = x + (size_t)row * DM;
    float4 v = *(const float4*)(xr + tid * 4);
    float s = v.x * v.x + v.y * v.y + v.z * v.z + v.w * v.w;
    #pragma unroll
    for (int off = 16; off; off >>= 1)
        s += __shfl_xor_sync(0xffffffffu, s, off);
    __shared__ float red[8];
    if ((tid & 31) == 0) red[tid >> 5] = s;
    __syncthreads();
    float tot = red[0] + red[1] + red[2] + red[3] +
                red[4] + red[5] + red[6] + red[7];
    float inv = rsqrtf(tot * (1.0f / DM) + 1e-5f);
    float4 wv = *(const float4*)(w + tid * 4);
    size_t o = (size_t)row * DM + tid * 4;
    split1(v.x * inv * wv.x, hi, lo, o + 0);
    split1(v.y * inv * wv.y, hi, lo, o + 1);
    split1(v.z * inv * wv.z, hi, lo, o + 2);
    split1(v.w * inv * wv.w, hi, lo, o + 3);
}

__global__ __launch_bounds__(256)
void rope_kernel(float* __restrict__ q, float* __restrict__ k) {
    int idx = blockIdx.x * blockDim.x + threadIdx.x;
    if (idx >= M_ROWS * 512) return;
    int m  = idx >> 9;
    int pir = idx & 511;
    int h  = pir >> 5;
    int pp = pir & 31;
    int s  = m & (SEQ - 1);
    float inv_freq = expf(-(float)(2 * pp) * (9.210340371976184f / 64.0f));
    float ang = (float)s * inv_freq;
    float sn, cs;
    sincosf(ang, &sn, &cs);
    size_t off = (size_t)m * DM + h * HD + 2 * pp;
    float qe = q[off], qo = q[off + 1];
    q[off]     = qe * cs - qo * sn;
    q[off + 1] = qo * cs + qe * sn;
    float ke = k[off], ko = k[off + 1];
    k[off]     = ke * cs - ko * sn;
    k[off + 1] = ko * cs + ke * sn;
}

// ---------------------------------------------------------------------------
// mma / ldmatrix / cp.async primitives
// ---------------------------------------------------------------------------
__device__ __forceinline__ void mma16(float* d, const unsigned* a,
                                      const unsigned* b) {
    asm volatile(
        "mma.sync.aligned.m16n8k16.row.col.f32.bf16.bf16.f32 "
        "{%0,%1,%2,%3}, {%4,%5,%6,%7}, {%8,%9}, {%0,%1,%2,%3};"
        : "+f"(d[0]), "+f"(d[1]), "+f"(d[2]), "+f"(d[3])
        : "r"(a[0]), "r"(a[1]), "r"(a[2]), "r"(a[3]), "r"(b[0]), "r"(b[1]));
}
__device__ __forceinline__ void ldmx4(unsigned* r, uint32_t addr) {
    asm volatile(
        "ldmatrix.sync.aligned.m8n8.x4.shared.b16 {%0,%1,%2,%3}, [%4];"
        : "=r"(r[0]), "=r"(r[1]), "=r"(r[2]), "=r"(r[3]) : "r"(addr));
}
__device__ __forceinline__ void ldmx4t(unsigned* r, uint32_t addr) {
    asm volatile(
        "ldmatrix.sync.aligned.m8n8.x4.trans.shared.b16 {%0,%1,%2,%3}, [%4];"
        : "=r"(r[0]), "=r"(r[1]), "=r"(r[2]), "=r"(r[3]) : "r"(addr));
}
__device__ __forceinline__ void cp_async16(uint32_t s, const void* g) {
    asm volatile("cp.async.cg.shared.global [%0], [%1], 16;\n"
                 :: "r"(s), "l"(g));
}
__device__ __forceinline__ void cp_commit() {
    asm volatile("cp.async.commit_group;\n");
}
__device__ __forceinline__ void cp_wait0() {
    asm volatile("cp.async.wait_group 0;\n");
}

// ---------------------------------------------------------------------------
// bf16 split-compensated GEMM, ldmatrix loads, dependency-aware mma schedule.
// C[M,N] = A[M,K] * W[N,K]^T (+epilogue); D += Ah*Wh + Al*Wh + Ah*Wl.
// 128x128x32 tile, 256 thr (8 warps 2x4, 64x32 warp tile), mma.m16n8k16.
// Inner loop emits mmas in 3 term-passes over mt-pairs so no accumulator is
// revisited within 8 consecutive HMMAs (breaks RAW chains).
// EPI: 0 C=AB; 1 C=AB+aux; 2 (Ch,Cl)=split(silu(AB)*aux)
// ---------------------------------------------------------------------------
template <int EPI>
__global__ __launch_bounds__(256, 1)
void bgemm_kernel(const bf16* __restrict__ Ah, const bf16* __restrict__ Al,
                  const bf16* __restrict__ Wh, const bf16* __restrict__ Wl,
                  float* __restrict__ C, bf16* __restrict__ Ch,
                  bf16* __restrict__ Cl, const float* __restrict__ aux,
                  int N, int K) {
    extern __shared__ char smc[];
    int tid = threadIdx.x;
    int wid = tid >> 5, lane = tid & 31;
    int g = lane >> 2, t = lane & 3;
    int wm = wid >> 2, wn = wid & 3;
    int m0 = blockIdx.y * 128;
    int n0 = blockIdx.x * 128;

    uint32_t smem_base = (uint32_t)__cvta_generic_to_shared(smc);

    // ldmatrix lane roles
    int mm = lane >> 3;
    int aRowLoc = (mm & 1) * 8 + (lane & 7);
    int aCb = mm >> 1;
    int bRowLoc = (mm >> 1) * 8 + (lane & 7);
    int bCb = mm & 1;

    uint32_t aOff[4]; int aSw[4];
    #pragma unroll
    for (int mt = 0; mt < 4; ++mt) {
        int r = wm * 64 + mt * 16 + aRowLoc;
        aOff[mt] = r * 64;
        aSw[mt] = (r >> 1) & 3;
    }
    uint32_t bOff[2]; int bSw[2];
    #pragma unroll
    for (int nt2 = 0; nt2 < 2; ++nt2) {
        int r = wn * 32 + nt2 * 16 + bRowLoc;
        bOff[nt2] = r * 64;
        bSw[nt2] = (r >> 1) & 3;
    }

    float acc[4][4][4];
    #pragma unroll
    for (int i = 0; i < 4; ++i)
        #pragma unroll
        for (int j = 0; j < 4; ++j)
            #pragma unroll
            for (int c = 0; c < 4; ++c) acc[i][j][c] = 0.0f;

    int niter = K >> 5;
    int grow = tid >> 1;
    int gch0 = (tid & 1) << 1;

    #define STAGE(buf, k0)                                                      \
    {                                                                           \
        _Pragma("unroll")                                                       \
        for (int cc = 0; cc < 2; ++cc) {                                        \
            int ch = gch0 + cc;                                                 \
            uint32_t soff = (uint32_t)(grow * 64 +                              \
                ((ch ^ ((grow >> 1) & 3)) << 4));                               \
            size_t ga = (size_t)(m0 + grow) * K + (k0) + ch * 8;                \
            size_t gb = (size_t)(n0 + grow) * K + (k0) + ch * 8;                \
            uint32_t sb = smem_base + (buf) * 32768 + soff;                     \
            cp_async16(sb,         Ah + ga);                                    \
            cp_async16(sb + 8192,  Al + ga);                                    \
            cp_async16(sb + 16384, Wh + gb);                                    \
            cp_async16(sb + 24576, Wl + gb);                                    \
        }                                                                       \
        cp_commit();                                                            \
    }

    STAGE(0, 0);
    cp_wait0();
    __syncthreads();

    int buf = 0;
    for (int it = 0; it < niter; ++it) {
        if (it + 1 < niter) STAGE(buf ^ 1, (it + 1) << 5);

        uint32_t tAh = smem_base + buf * 32768;
        uint32_t tAl = tAh + 8192;
        uint32_t tBh = tAh + 16384;
        uint32_t tBl = tAh + 24576;

        #pragma unroll
        for (int ck = 0; ck < 2; ++ck) {
            unsigned bhf[2][4], blf[2][4];
            #pragma unroll
            for (int nt2 = 0; nt2 < 2; ++nt2) {
                uint32_t off = bOff[nt2] +
                               (((2 * ck + bCb) ^ bSw[nt2]) << 4);
                ldmx4(bhf[nt2], tBh + off);
                ldmx4(blf[nt2], tBl + off);
            }
            #pragma unroll
            for (int mp = 0; mp < 2; ++mp) {
                int mt0 = 2 * mp, mt1 = 2 * mp + 1;
                uint32_t off0 = aOff[mt0] + (((2 * ck + aCb) ^ aSw[mt0]) << 4);
                uint32_t off1 = aOff[mt1] + (((2 * ck + aCb) ^ aSw[mt1]) << 4);
                unsigned ah0[4], al0[4], ah1[4], al1[4];
                ldmx4(ah0, tAh + off0);
                ldmx4(ah1, tAh + off1);
                ldmx4(al0, tAl + off0);
                ldmx4(al1, tAl + off1);
                // pass 1: hi*hi  (8 mmas, 8 distinct accumulators)
                mma16(acc[mt0][0], ah0, bhf[0]);
                mma16(acc[mt0][1], ah0, bhf[0] + 2);
                mma16(acc[mt0][2], ah0, bhf[1]);
                mma16(acc[mt0][3], ah0, bhf[1] + 2);
                mma16(acc[mt1][0], ah1, bhf[0]);
                mma16(acc[mt1][1], ah1, bhf[0] + 2);
                mma16(acc[mt1][2], ah1, bhf[1]);
                mma16(acc[mt1][3], ah1, bhf[1] + 2);
                // pass 2: lo*hi
                mma16(acc[mt0][0], al0, bhf[0]);
                mma16(acc[mt0][1], al0, bhf[0] + 2);
                mma16(acc[mt0][2], al0, bhf[1]);
                mma16(acc[mt0][3], al0, bhf[1] + 2);
                mma16(acc[mt1][0], al1, bhf[0]);
                mma16(acc[mt1][1], al1, bhf[0] + 2);
                mma16(acc[mt1][2], al1, bhf[1]);
                mma16(acc[mt1][3], al1, bhf[1] + 2);
                // pass 3: hi*lo
                mma16(acc[mt0][0], ah0, blf[0]);
                mma16(acc[mt0][1], ah0, blf[0] + 2);
                mma16(acc[mt0][2], ah0, blf[1]);
                mma16(acc[mt0][3], ah0, blf[1] + 2);
                mma16(acc[mt1][0], ah1, blf[0]);
                mma16(acc[mt1][1], ah1, blf[0] + 2);
                mma16(acc[mt1][2], ah1, blf[1]);
                mma16(acc[mt1][3], ah1, blf[1] + 2);
            }
        }

        if (it + 1 < niter) cp_wait0();
        __syncthreads();
        buf ^= 1;
    }
    #undef STAGE

    #pragma unroll
    for (int mt = 0; mt < 4; ++mt) {
        #pragma unroll
        for (int nt = 0; nt < 4; ++nt) {
            int rb = m0 + wm * 64 + mt * 16 + g;
            int cb = n0 + wn * 32 + nt * 8 + 2 * t;
            #pragma unroll
            for (int half = 0; half < 2; ++half) {
                size_t off = (size_t)(rb + half * 8) * N + cb;
                #pragma unroll
                for (int e = 0; e < 2; ++e) {
                    float u = acc[mt][nt][half * 2 + e];
                    if (EPI == 0) {
                        C[off + e] = u;
                    } else if (EPI == 1) {
                        C[off + e] = u + aux[off + e];
                    } else {
                        float sg = 1.0f / (1.0f + __expf(-u));
                        float r = u * sg * aux[off + e];
                        split1(r, Ch, Cl, off + e);
                    }
                }
            }
        }
    }
}

// ---------------------------------------------------------------------------
// Tensor-core flash attention (causal), bf16 split-compensated,
// dependency-interleaved mma schedule (nt pairs in S, alternating accs in PV).
// ---------------------------------------------------------------------------
__global__ __launch_bounds__(256, 1)
void flash_kernel(const float* __restrict__ q, const float* __restrict__ k,
                  const float* __restrict__ v,
                  bf16* __restrict__ aoh, bf16* __restrict__ aol) {
    extern __shared__ char sm[];
    char* Qh = sm;
    char* Ql = sm + 16384;
    char* Kh = sm + 32768;
    char* Kl = sm + 40960;
    char* Vh = sm + 49152;
    char* Vl = sm + 57344;
    uint32_t uQh = (uint32_t)__cvta_generic_to_shared(Qh);
    uint32_t uQl = uQh + 16384;
    uint32_t uKh = uQh + 32768;
    uint32_t uKl = uQh + 40960;
    uint32_t uVh = uQh + 49152;
    uint32_t uVl = uQh + 57344;

    int tid = threadIdx.x;
    int wid = tid >> 5, lane = tid & 31;
    int g = lane >> 2, t = lane & 3;
    int qb = blockIdx.x;
    int bh = blockIdx.y;
    int b = bh >> 4, h = bh & 15;
    int i0 = qb * 128;
    size_t base = ((size_t)b * SEQ) * DM + h * HD;

    {
        int row = tid >> 1;
        int d0 = (tid & 1) * 32;
        const float* qg = q + base + (size_t)(i0 + row) * DM + d0;
        #pragma unroll
        for (int c = 0; c < 4; ++c) {
            float4 f0 = *(const float4*)(qg + c * 8);
            float4 f1 = *(const float4*)(qg + c * 8 + 4);
            uint4 hh, ll;
            split_pack(f0.x, f0.y, hh.x, ll.x);
            split_pack(f0.z, f0.w, hh.y, ll.y);
            split_pack(f1.x, f1.y, hh.z, ll.z);
            split_pack(f1.z, f1.w, hh.w, ll.w);
            int chunk = (d0 >> 3) + c;
            int off = row * 128 + ((chunk ^ (row & 7)) << 4);
            *(uint4*)(Qh + off) = hh;
            *(uint4*)(Ql + off) = ll;
        }
    }
    __syncthreads();

    int r0 = 16 * wid;
    unsigned aqh[4][4], aql[4][4];
    #pragma unroll
    for (int kc = 0; kc < 4; ++kc) {
        int m = lane >> 3;
        int lr = r0 + (lane & 7) + (m & 1) * 8;
        int lc = (2 * kc + (m >> 1)) ^ (lr & 7);
        ldmx4(aqh[kc], uQh + lr * 128 + lc * 16);
        ldmx4(aql[kc], uQl + lr * 128 + lc * 16);
    }

    float oacc[8][4];
    #pragma unroll
    for (int i = 0; i < 8; ++i)
        #pragma unroll
        for (int c = 0; c < 4; ++c) oacc[i][c] = 0.0f;
    float mrow0 = -1e30f, mrow1 = -1e30f;
    float lrow0 = 0.0f, lrow1 = 0.0f;

    int rowg0 = i0 + r0 + g;
    int ntiles = 2 * qb + 2;
    int nfull  = 2 * qb;

    for (int j = 0; j < ntiles; ++j) {
        __syncthreads();
        {
            int row = tid >> 2;
            int d0 = (tid & 3) * 16;
            const float* kg = k + base + (size_t)(j * 64 + row) * DM + d0;
            const float* vg = v + base + (size_t)(j * 64 + row) * DM + d0;
            #pragma unroll
            for (int c = 0; c < 2; ++c) {
                float4 f0 = *(const float4*)(kg + c * 8);
                float4 f1 = *(const float4*)(kg + c * 8 + 4);
                uint4 hh, ll;
                split_pack(f0.x, f0.y, hh.x, ll.x);
                split_pack(f0.z, f0.w, hh.y, ll.y);
                split_pack(f1.x, f1.y, hh.z, ll.z);
                split_pack(f1.z, f1.w, hh.w, ll.w);
                int chunk = (d0 >> 3) + c;
                int off = row * 128 + ((chunk ^ (row & 7)) << 4);
                *(uint4*)(Kh + off) = hh;
                *(uint4*)(Kl + off) = ll;
                float4 g0 = *(const float4*)(vg + c * 8);
                float4 g1 = *(const float4*)(vg + c * 8 + 4);
                split_pack(g0.x, g0.y, hh.x, ll.x);
                split_pack(g0.z, g0.w, hh.y, ll.y);
                split_pack(g1.x, g1.y, hh.z, ll.z);
                split_pack(g1.z, g1.w, hh.w, ll.w);
                *(uint4*)(Vh + off) = hh;
                *(uint4*)(Vl + off) = ll;
            }
        }
        __syncthreads();

        float sacc[8][4];
        #pragma unroll
        for (int i = 0; i < 8; ++i)
            #pragma unroll
            for (int c = 0; c < 4; ++c) sacc[i][c] = 0.0f;

        // S = Q K^T, nt processed in pairs; mmas alternate between the two
        // accumulators so same-acc reuse distance is 2 instead of 1.
        #pragma unroll
        for (int nt = 0; nt < 8; nt += 2) {
            #pragma unroll
            for (int p = 0; p < 2; ++p) {
                int lr0 = 8 * nt + (lane & 7);
                int lc0 = (4 * p + (lane >> 3)) ^ (lr0 & 7);
                int lr1 = 8 * (nt + 1) + (lane & 7);
                int lc1 = (4 * p + (lane >> 3)) ^ (lr1 & 7);
                unsigned bkh0[4], bkl0[4], bkh1[4], bkl1[4];
                ldmx4(bkh0, uKh + lr0 * 128 + lc0 * 16);
                ldmx4(bkh1, uKh + lr1 * 128 + lc1 * 16);
                ldmx4(bkl0, uKl + lr0 * 128 + lc0 * 16);
                ldmx4(bkl1, uKl + lr1 * 128 + lc1 * 16);
                mma16(sacc[nt],     aqh[2 * p],     bkh0);
                mma16(sacc[nt + 1], aqh[2 * p],     bkh1);
                mma16(sacc[nt],     aql[2 * p],     bkh0);
                mma16(sacc[nt + 1], aql[2 * p],     bkh1);
                mma16(sacc[nt],     aqh[2 * p],     bkl0);
                mma16(sacc[nt + 1], aqh[2 * p],     bkl1);
                mma16(sacc[nt],     aqh[2 * p + 1], bkh0 + 2);
                mma16(sacc[nt + 1], aqh[2 * p + 1], bkh1 + 2);
                mma16(sacc[nt],     aql[2 * p + 1], bkh0 + 2);
                mma16(sacc[nt + 1], aql[2 * p + 1], bkh1 + 2);
                mma16(sacc[nt],     aqh[2 * p + 1], bkl0 + 2);
                mma16(sacc[nt + 1], aqh[2 * p + 1], bkl1 + 2);
            }
        }

        bool masked = (j >= nfull);
        int jb = j * 64;
        #pragma unroll
        for (int nt = 0; nt < 8; ++nt) {
            #pragma unroll
            for (int c = 0; c < 4; ++c) {
                float val = sacc[nt][c] * 0.125f;
                if (masked) {
                    int col = jb + 8 * nt + 2 * t + (c & 1);
                    int row = rowg0 + ((c >> 1) << 3);
                    if (col > row) val = -1e30f;
                }
                sacc[nt][c] = val;
            }
        }

        float m0 = -1e30f, m1 = -1e30f;
        #pragma unroll
        for (int nt = 0; nt < 8; ++nt) {
            m0 = fmaxf(m0, fmaxf(sacc[nt][0], sacc[nt][1]));
            m1 = fmaxf(m1, fmaxf(sacc[nt][2], sacc[nt][3]));
        }
        m0 = fmaxf(m0, __shfl_xor_sync(0xffffffffu, m0, 1));
        m0 = fmaxf(m0, __shfl_xor_sync(0xffffffffu, m0, 2));
        m1 = fmaxf(m1, __shfl_xor_sync(0xffffffffu, m1, 1));
        m1 = fmaxf(m1, __shfl_xor_sync(0xffffffffu, m1, 2));
        float mn0 = fmaxf(mrow0, m0);
        float mn1 = fmaxf(mrow1, m1);
        float corr0 = __expf(mrow0 - mn0);
        float corr1 = __expf(mrow1 - mn1);
        mrow0 = mn0; mrow1 = mn1;

        unsigned ph01[8], pl01[8], ph23[8], pl23[8];
        float rs0 = 0.0f, rs1 = 0.0f;
        #pragma unroll
        for (int nt = 0; nt < 8; ++nt) {
            float p0 = __expf(sacc[nt][0] - mn0);
            float p1 = __expf(sacc[nt][1] - mn0);
            float p2 = __expf(sacc[nt][2] - mn1);
            float p3 = __expf(sacc[nt][3] - mn1);
            rs0 += p0 + p1;
            rs1 += p2 + p3;
            split_pack(p0, p1, ph01[nt], pl01[nt]);
            split_pack(p2, p3, ph23[nt], pl23[nt]);
        }
        rs0 += __shfl_xor_sync(0xffffffffu, rs0, 1);
        rs0 += __shfl_xor_sync(0xffffffffu, rs0, 2);
        rs1 += __shfl_xor_sync(0xffffffffu, rs1, 1);
        rs1 += __shfl_xor_sync(0xffffffffu, rs1, 2);
        lrow0 = lrow0 * corr0 + rs0;
        lrow1 = lrow1 * corr1 + rs1;
        #pragma unroll
        for (int nd = 0; nd < 8; ++nd) {
            oacc[nd][0] *= corr0; oacc[nd][1] *= corr0;
            oacc[nd][2] *= corr1; oacc[nd][3] *= corr1;
        }

        // O += P V, alternating between the two output accumulators.
        #pragma unroll
        for (int kc = 0; kc < 4; ++kc) {
            unsigned pah[4] = { ph01[2 * kc], ph23[2 * kc],
                                ph01[2 * kc + 1], ph23[2 * kc + 1] };
            unsigned pal[4] = { pl01[2 * kc], pl23[2 * kc],
                                pl01[2 * kc + 1], pl23[2 * kc + 1] };
            #pragma unroll
            for (int nd2 = 0; nd2 < 4; ++nd2) {
                int lr = 16 * kc + (lane & 15);
                int lc = (2 * nd2 + (lane >> 4)) ^ (lr & 7);
                unsigned bvh[4], bvl[4];
                ldmx4t(bvh, uVh + lr * 128 + lc * 16);
                ldmx4t(bvl, uVl + lr * 128 + lc * 16);
                mma16(oacc[2 * nd2],     pah, bvh);
                mma16(oacc[2 * nd2 + 1], pah, bvh + 2);
                mma16(oacc[2 * nd2],     pal, bvh);
                mma16(oacc[2 * nd2 + 1], pal, bvh + 2);
                mma16(oacc[2 * nd2],     pah, bvl);
                mma16(oacc[2 * nd2 + 1], pah, bvl + 2);
            }
        }
    }

    float inv0 = 1.0f / lrow0;
    float inv1 = 1.0f / lrow1;
    #pragma unroll
    for (int nd = 0; nd < 8; ++nd) {
        int col = 8 * nd + 2 * t;
        size_t off0 = base + (size_t)(rowg0) * DM + col;
        size_t off1 = base + (size_t)(rowg0 + 8) * DM + col;
        unsigned hw, lw;
        split_pack(oacc[nd][0] * inv0, oacc[nd][1] * inv0, hw, lw);
        *(unsigned*)(aoh + off0) = hw;
        *(unsigned*)(aol + off0) = lw;
        split_pack(oacc[nd][2] * inv1, oacc[nd][3] * inv1, hw, lw);
        *(unsigned*)(aoh + off1) = hw;
        *(unsigned*)(aol + off1) = lw;
    }
}

// ---------------------------------------------------------------------------
// Launch
// ---------------------------------------------------------------------------
extern "C" void kernel_launch(void* const* d_in, const int* in_sizes, int n_in,
                              void* d_out, int out_size) {
    const float* x     = (const float*)d_in[0];
    const float* wq    = (const float*)d_in[1];
    const float* wk    = (const float*)d_in[2];
    const float* wv    = (const float*)d_in[3];
    const float* wo    = (const float*)d_in[4];
    const float* ln1w  = (const float*)d_in[5];
    const float* ln2w  = (const float*)d_in[6];
    const float* upw   = (const float*)d_in[7];
    const float* gatew = (const float*)d_in[8];
    const float* downw = (const float*)d_in[9];
    float* out = (float*)d_out;

    float *q, *k, *v, *x1, *gate;
    cudaGetSymbolAddress((void**)&q,    g_q);
    cudaGetSymbolAddress((void**)&k,    g_k);
    cudaGetSymbolAddress((void**)&v,    g_v);
    cudaGetSymbolAddress((void**)&x1,   g_x1);
    cudaGetSymbolAddress((void**)&gate, g_gate);

    bf16 *xnh, *xnl, *aoh, *aol, *hh, *hl;
    bf16 *wqh, *wql, *wkh, *wkl, *wvh, *wvl, *woh, *wol;
    bf16 *uph, *upl, *gwh, *gwl, *dwh, *dwl;
    cudaGetSymbolAddress((void**)&xnh, g_xnh);
    cudaGetSymbolAddress((void**)&xnl, g_xnl);
    cudaGetSymbolAddress((void**)&aoh, g_aoh);
    cudaGetSymbolAddress((void**)&aol, g_aol);
    cudaGetSymbolAddress((void**)&hh,  g_hh);
    cudaGetSymbolAddress((void**)&hl,  g_hl);
    cudaGetSymbolAddress((void**)&wqh, g_wqh);
    cudaGetSymbolAddress((void**)&wql, g_wql);
    cudaGetSymbolAddress((void**)&wkh, g_wkh);
    cudaGetSymbolAddress((void**)&wkl, g_wkl);
    cudaGetSymbolAddress((void**)&wvh, g_wvh);
    cudaGetSymbolAddress((void**)&wvl, g_wvl);
    cudaGetSymbolAddress((void**)&woh, g_woh);
    cudaGetSymbolAddress((void**)&wol, g_wol);
    cudaGetSymbolAddress((void**)&uph, g_uph);
    cudaGetSymbolAddress((void**)&upl, g_upl);
    cudaGetSymbolAddress((void**)&gwh, g_gwh);
    cudaGetSymbolAddress((void**)&gwl, g_gwl);
    cudaGetSymbolAddress((void**)&dwh, g_dwh);
    cudaGetSymbolAddress((void**)&dwl, g_dwl);

    cudaFuncSetAttribute(flash_kernel,
                         cudaFuncAttributeMaxDynamicSharedMemorySize, 65536);
    cudaFuncSetAttribute(bgemm_kernel<0>,
                         cudaFuncAttributeMaxDynamicSharedMemorySize, 65536);
    cudaFuncSetAttribute(bgemm_kernel<1>,
                         cudaFuncAttributeMaxDynamicSharedMemorySize, 65536);
    cudaFuncSetAttribute(bgemm_kernel<2>,
                         cudaFuncAttributeMaxDynamicSharedMemorySize, 65536);

    dim3 g1(DM / 128, M_ROWS / 128);    // (8, 64)
    dim3 g2(DFF / 128, M_ROWS / 128);   // (32, 64)

    // Weight splits
    split_kernel<<<DM * DM / 1024, 256>>>(wq, wqh, wql);
    split_kernel<<<DM * DM / 1024, 256>>>(wk, wkh, wkl);
    split_kernel<<<DM * DM / 1024, 256>>>(wv, wvh, wvl);
    split_kernel<<<DM * DM / 1024, 256>>>(wo, woh, wol);
    split_kernel<<<DFF * DM / 1024, 256>>>(upw, uph, upl);
    split_kernel<<<DFF * DM / 1024, 256>>>(gatew, gwh, gwl);
    split_kernel<<<DM * DFF / 1024, 256>>>(downw, dwh, dwl);

    // ln1 -> split xn
    rmsnorm_split_kernel<<<M_ROWS, 256>>>(x, ln1w, xnh, xnl);
    // q, k, v projections
    bgemm_kernel<0><<<g1, 256, 65536>>>(xnh, xnl, wqh, wql, q, nullptr, nullptr, nullptr, DM, DM);
    bgemm_kernel<0><<<g1, 256, 65536>>>(xnh, xnl, wkh, wkl, k, nullptr, nullptr, nullptr, DM, DM);
    bgemm_kernel<0><<<g1, 256, 65536>>>(xnh, xnl, wvh, wvl, v, nullptr, nullptr, nullptr, DM, DM);
    rope_kernel<<<(M_ROWS * 512) / 256, 256>>>(q, k);
    // tensor-core flash attention (writes split ao directly)
    flash_kernel<<<dim3(SEQ / 128, B_SZ * NHEAD), 256, 65536>>>(q, k, v, aoh, aol);
    // o projection + residual
    bgemm_kernel<1><<<g1, 256, 65536>>>(aoh, aol, woh, wol, x1, nullptr, nullptr, x, DM, DM);
    // ln2 -> split
    rmsnorm_split_kernel<<<M_ROWS, 256>>>(x1, ln2w, xnh, xnl);
    // FFN
    bgemm_kernel<0><<<g2, 256, 65536>>>(xnh, xnl, gwh, gwl, gate, nullptr, nullptr, nullptr, DFF, DM);
    bgemm_kernel<2><<<g2, 256, 65536>>>(xnh, xnl, uph, upl, nullptr, hh, hl, gate, DFF, DM);
    bgemm_kernel<1><<<g1, 256, 65536>>>(hh, hl, dwh, dwl, out, nullptr, nullptr, x1, DM, DFF);
}

// round 12
// speedup vs baseline: 1.2839x; 1.2839x over previous
#include <cuda_runtime.h>
#include <cuda_bf16.h>
#include <cuda_fp16.h>
#include <math.h>
#include <stdint.h>

// Problem constants
#define B_SZ 4
#define SEQ 2048
#define DM 1024
#define NHEAD 16
#define HD 64
#define DFF 4096
#define M_ROWS (B_SZ * SEQ)   // 8192

typedef __nv_bfloat16 bf16;
typedef __half f16;

// ---------------------------------------------------------------------------
// Scratch buffers
// ---------------------------------------------------------------------------
__device__ float g_q[M_ROWS * DM];
__device__ float g_k[M_ROWS * DM];
__device__ float g_v[M_ROWS * DM];
__device__ float g_x1[M_ROWS * DM];
__device__ float g_gate[M_ROWS * DFF];

__device__ f16 g_xnh[M_ROWS * DM],  g_xnl[M_ROWS * DM];
__device__ f16 g_aoh[M_ROWS * DM],  g_aol[M_ROWS * DM];
__device__ f16 g_hh[M_ROWS * DFF],  g_hl[M_ROWS * DFF];

__device__ f16 g_wq16[DM * DM];
__device__ f16 g_wk16[DM * DM];
__device__ f16 g_wv16[DM * DM];
__device__ f16 g_wo16[DM * DM];
__device__ f16 g_up16[DFF * DM];
__device__ f16 g_gw16[DFF * DM];
__device__ f16 g_dw16[DM * DFF];

// fp16 split helpers
__device__ __forceinline__ void split1h(float r, f16* hi, f16* lo, size_t off) {
    f16 h = __float2half_rn(r);
    hi[off] = h;
    lo[off] = __float2half_rn(r - __half2float(h));
}
__device__ __forceinline__ void split_pack_h(float f0, float f1,
                                             unsigned& h, unsigned& l) {
    f16 h0 = __float2half_rn(f0), h1 = __float2half_rn(f1);
    unsigned short u0 = *(unsigned short*)&h0, u1 = *(unsigned short*)&h1;
    h = ((unsigned)u1 << 16) | u0;
    f16 l0 = __float2half_rn(f0 - __half2float(h0));
    f16 l1 = __float2half_rn(f1 - __half2float(h1));
    unsigned short v0 = *(unsigned short*)&l0, v1 = *(unsigned short*)&l1;
    l = ((unsigned)v1 << 16) | v0;
}
// bf16 pack (flash internal staging)
__device__ __forceinline__ void split_pack(float f0, float f1,
                                           unsigned& h, unsigned& l) {
    bf16 h0 = __float2bfloat16(f0), h1 = __float2bfloat16(f1);
    unsigned short u0 = *(unsigned short*)&h0, u1 = *(unsigned short*)&h1;
    h = ((unsigned)u1 << 16) | u0;
    bf16 l0 = __float2bfloat16(f0 - __bfloat162float(h0));
    bf16 l1 = __float2bfloat16(f1 - __bfloat162float(h1));
    unsigned short v0 = *(unsigned short*)&l0, v1 = *(unsigned short*)&l1;
    l = ((unsigned)v1 << 16) | v0;
}

// ---------------------------------------------------------------------------
// Elementwise kernels
// ---------------------------------------------------------------------------
// fp32 -> fp16 (weights)
__global__ __launch_bounds__(256)
void cvt16_kernel(const float* __restrict__ src, f16* __restrict__ dst) {
    size_t i = ((size_t)blockIdx.x * 256 + threadIdx.x) * 4;
    float4 v = *(const float4*)(src + i);
    __half2 a = __floats2half2_rn(v.x, v.y);
    __half2 b = __floats2half2_rn(v.z, v.w);
    *(__half2*)(dst + i) = a;
    *(__half2*)(dst + i + 2) = b;
}

__global__ __launch_bounds__(256)
void rmsnorm_split_kernel(const float* __restrict__ x,
                          const float* __restrict__ w,
                          f16* __restrict__ hi, f16* __restrict__ lo) {
    int row = blockIdx.x;
    int tid = threadIdx.x;
    const float* xr = x + (size_t)row * DM;
    float4 v = *(const float4*)(xr + tid * 4);
    float s = v.x * v.x + v.y * v.y + v.z * v.z + v.w * v.w;
    #pragma unroll
    for (int off = 16; off; off >>= 1)
        s += __shfl_xor_sync(0xffffffffu, s, off);
    __shared__ float red[8];
    if ((tid & 31) == 0) red[tid >> 5] = s;
    __syncthreads();
    float tot = red[0] + red[1] + red[2] + red[3] +
                red[4] + red[5] + red[6] + red[7];
    float inv = rsqrtf(tot * (1.0f / DM) + 1e-5f);
    float4 wv = *(const float4*)(w + tid * 4);
    size_t o = (size_t)row * DM + tid * 4;
    split1h(v.x * inv * wv.x, hi, lo, o + 0);
    split1h(v.y * inv * wv.y, hi, lo, o + 1);
    split1h(v.z * inv * wv.z, hi, lo, o + 2);
    split1h(v.w * inv * wv.w, hi, lo, o + 3);
}

__global__ __launch_bounds__(256)
void rope_kernel(float* __restrict__ q, float* __restrict__ k) {
    int idx = blockIdx.x * blockDim.x + threadIdx.x;
    if (idx >= M_ROWS * 512) return;
    int m  = idx >> 9;
    int pir = idx & 511;
    int h  = pir >> 5;
    int pp = pir & 31;
    int s  = m & (SEQ - 1);
    float inv_freq = expf(-(float)(2 * pp) * (9.210340371976184f / 64.0f));
    float ang = (float)s * inv_freq;
    float sn, cs;
    sincosf(ang, &sn, &cs);
    size_t off = (size_t)m * DM + h * HD + 2 * pp;
    float qe = q[off], qo = q[off + 1];
    q[off]     = qe * cs - qo * sn;
    q[off + 1] = qo * cs + qe * sn;
    float ke = k[off], ko = k[off + 1];
    k[off]     = ke * cs - ko * sn;
    k[off + 1] = ko * cs + ke * sn;
}

// ---------------------------------------------------------------------------
// mma / ldmatrix / cp.async primitives
// ---------------------------------------------------------------------------
__device__ __forceinline__ void mma16(float* d, const unsigned* a,
                                      const unsigned* b) {
    asm volatile(
        "mma.sync.aligned.m16n8k16.row.col.f32.bf16.bf16.f32 "
        "{%0,%1,%2,%3}, {%4,%5,%6,%7}, {%8,%9}, {%0,%1,%2,%3};"
        : "+f"(d[0]), "+f"(d[1]), "+f"(d[2]), "+f"(d[3])
        : "r"(a[0]), "r"(a[1]), "r"(a[2]), "r"(a[3]), "r"(b[0]), "r"(b[1]));
}
__device__ __forceinline__ void mma16h(float* d, const unsigned* a,
                                       const unsigned* b) {
    asm volatile(
        "mma.sync.aligned.m16n8k16.row.col.f32.f16.f16.f32 "
        "{%0,%1,%2,%3}, {%4,%5,%6,%7}, {%8,%9}, {%0,%1,%2,%3};"
        : "+f"(d[0]), "+f"(d[1]), "+f"(d[2]), "+f"(d[3])
        : "r"(a[0]), "r"(a[1]), "r"(a[2]), "r"(a[3]), "r"(b[0]), "r"(b[1]));
}
__device__ __forceinline__ void ldmx4(unsigned* r, uint32_t addr) {
    asm volatile(
        "ldmatrix.sync.aligned.m8n8.x4.shared.b16 {%0,%1,%2,%3}, [%4];"
        : "=r"(r[0]), "=r"(r[1]), "=r"(r[2]), "=r"(r[3]) : "r"(addr));
}
__device__ __forceinline__ void ldmx4t(unsigned* r, uint32_t addr) {
    asm volatile(
        "ldmatrix.sync.aligned.m8n8.x4.trans.shared.b16 {%0,%1,%2,%3}, [%4];"
        : "=r"(r[0]), "=r"(r[1]), "=r"(r[2]), "=r"(r[3]) : "r"(addr));
}
__device__ __forceinline__ void cp_async16(uint32_t s, const void* g) {
    asm volatile("cp.async.cg.shared.global [%0], [%1], 16;\n"
                 :: "r"(s), "l"(g));
}
__device__ __forceinline__ void cp_commit() {
    asm volatile("cp.async.commit_group;\n");
}
__device__ __forceinline__ void cp_wait0() {
    asm volatile("cp.async.wait_group 0;\n");
}

// ---------------------------------------------------------------------------
// fp16 2-term GEMM: C[M,N] = (Ah+Al)[M,K] * W16[N,K]^T (+epilogue)
// D += Ah*W + Al*W. 128x128x32 tile, 256 thr (8 warps 2x4, 64x32 warp tile).
// Smem/stage: Ah 8KB | Al 8KB | W 8KB = 24KB; double buffered = 48KB.
// Row: 32 f16 = 64B = 4 chunks of 16B, chunk' = chunk ^ ((row>>1)&3).
// EPI: 0 C=AB; 1 C=AB+aux; 2 (Ch,Cl)=split16(silu(AB)*aux)
// ---------------------------------------------------------------------------
template <int EPI>
__global__ __launch_bounds__(256, 1)
void hgemm_kernel(const f16* __restrict__ Ah, const f16* __restrict__ Al,
                  const f16* __restrict__ W,
                  float* __restrict__ C, f16* __restrict__ Ch,
                  f16* __restrict__ Cl, const float* __restrict__ aux,
                  int N, int K) {
    extern __shared__ char smc[];
    int tid = threadIdx.x;
    int wid = tid >> 5, lane = tid & 31;
    int g = lane >> 2, t = lane & 3;
    int wm = wid >> 2, wn = wid & 3;
    int m0 = blockIdx.y * 128;
    int n0 = blockIdx.x * 128;

    uint32_t smem_base = (uint32_t)__cvta_generic_to_shared(smc);

    // ldmatrix lane roles
    int mm = lane >> 3;
    int aRowLoc = (mm & 1) * 8 + (lane & 7);
    int aCb = mm >> 1;
    int bRowLoc = (mm >> 1) * 8 + (lane & 7);
    int bCb = mm & 1;

    uint32_t aOff[4]; int aSw[4];
    #pragma unroll
    for (int mt = 0; mt < 4; ++mt) {
        int r = wm * 64 + mt * 16 + aRowLoc;
        aOff[mt] = r * 64;
        aSw[mt] = (r >> 1) & 3;
    }
    uint32_t bOff[2]; int bSw[2];
    #pragma unroll
    for (int nt2 = 0; nt2 < 2; ++nt2) {
        int r = wn * 32 + nt2 * 16 + bRowLoc;
        bOff[nt2] = r * 64;
        bSw[nt2] = (r >> 1) & 3;
    }

    float acc[4][4][4];
    #pragma unroll
    for (int i = 0; i < 4; ++i)
        #pragma unroll
        for (int j = 0; j < 4; ++j)
            #pragma unroll
            for (int c = 0; c < 4; ++c) acc[i][j][c] = 0.0f;

    int niter = K >> 5;
    int grow = tid >> 1;
    int gch0 = (tid & 1) << 1;

    #define STAGE(buf, k0)                                                      \
    {                                                                           \
        _Pragma("unroll")                                                       \
        for (int cc = 0; cc < 2; ++cc) {                                        \
            int ch = gch0 + cc;                                                 \
            uint32_t soff = (uint32_t)(grow * 64 +                              \
                ((ch ^ ((grow >> 1) & 3)) << 4));                               \
            size_t ga = (size_t)(m0 + grow) * K + (k0) + ch * 8;                \
            size_t gb = (size_t)(n0 + grow) * K + (k0) + ch * 8;                \
            uint32_t sb = smem_base + (buf) * 24576 + soff;                     \
            cp_async16(sb,         Ah + ga);                                    \
            cp_async16(sb + 8192,  Al + ga);                                    \
            cp_async16(sb + 16384, W  + gb);                                    \
        }                                                                       \
        cp_commit();                                                            \
    }

    STAGE(0, 0);
    cp_wait0();
    __syncthreads();

    int buf = 0;
    for (int it = 0; it < niter; ++it) {
        if (it + 1 < niter) STAGE(buf ^ 1, (it + 1) << 5);

        uint32_t tAh = smem_base + buf * 24576;
        uint32_t tAl = tAh + 8192;
        uint32_t tB  = tAh + 16384;

        #pragma unroll
        for (int ck = 0; ck < 2; ++ck) {
            unsigned bf[2][4];
            #pragma unroll
            for (int nt2 = 0; nt2 < 2; ++nt2) {
                uint32_t off = bOff[nt2] +
                               (((2 * ck + bCb) ^ bSw[nt2]) << 4);
                ldmx4(bf[nt2], tB + off);
            }
            #pragma unroll
            for (int mp = 0; mp < 2; ++mp) {
                int mt0 = 2 * mp, mt1 = 2 * mp + 1;
                uint32_t off0 = aOff[mt0] + (((2 * ck + aCb) ^ aSw[mt0]) << 4);
                uint32_t off1 = aOff[mt1] + (((2 * ck + aCb) ^ aSw[mt1]) << 4);
                unsigned ah0[4], al0[4], ah1[4], al1[4];
                ldmx4(ah0, tAh + off0);
                ldmx4(ah1, tAh + off1);
                ldmx4(al0, tAl + off0);
                ldmx4(al1, tAl + off1);
                // pass 1: Ah*W  (8 mmas, 8 distinct accumulators)
                mma16h(acc[mt0][0], ah0, bf[0]);
                mma16h(acc[mt0][1], ah0, bf[0] + 2);
                mma16h(acc[mt0][2], ah0, bf[1]);
                mma16h(acc[mt0][3], ah0, bf[1] + 2);
                mma16h(acc[mt1][0], ah1, bf[0]);
                mma16h(acc[mt1][1], ah1, bf[0] + 2);
                mma16h(acc[mt1][2], ah1, bf[1]);
                mma16h(acc[mt1][3], ah1, bf[1] + 2);
                // pass 2: Al*W
                mma16h(acc[mt0][0], al0, bf[0]);
                mma16h(acc[mt0][1], al0, bf[0] + 2);
                mma16h(acc[mt0][2], al0, bf[1]);
                mma16h(acc[mt0][3], al0, bf[1] + 2);
                mma16h(acc[mt1][0], al1, bf[0]);
                mma16h(acc[mt1][1], al1, bf[0] + 2);
                mma16h(acc[mt1][2], al1, bf[1]);
                mma16h(acc[mt1][3], al1, bf[1] + 2);
            }
        }

        if (it + 1 < niter) cp_wait0();
        __syncthreads();
        buf ^= 1;
    }
    #undef STAGE

    #pragma unroll
    for (int mt = 0; mt < 4; ++mt) {
        #pragma unroll
        for (int nt = 0; nt < 4; ++nt) {
            int rb = m0 + wm * 64 + mt * 16 + g;
            int cb = n0 + wn * 32 + nt * 8 + 2 * t;
            #pragma unroll
            for (int half = 0; half < 2; ++half) {
                size_t off = (size_t)(rb + half * 8) * N + cb;
                #pragma unroll
                for (int e = 0; e < 2; ++e) {
                    float u = acc[mt][nt][half * 2 + e];
                    if (EPI == 0) {
                        C[off + e] = u;
                    } else if (EPI == 1) {
                        C[off + e] = u + aux[off + e];
                    } else {
                        float sg = 1.0f / (1.0f + __expf(-u));
                        float r = u * sg * aux[off + e];
                        split1h(r, Ch, Cl, off + e);
                    }
                }
            }
        }
    }
}

// ---------------------------------------------------------------------------
// Tensor-core flash attention (causal), bf16 split-compensated internals,
// fp16 split output (consumed by the wo fp16 GEMM).
// ---------------------------------------------------------------------------
__global__ __launch_bounds__(256, 1)
void flash_kernel(const float* __restrict__ q, const float* __restrict__ k,
                  const float* __restrict__ v,
                  f16* __restrict__ aoh, f16* __restrict__ aol) {
    extern __shared__ char sm[];
    char* Qh = sm;
    char* Ql = sm + 16384;
    char* Kh = sm + 32768;
    char* Kl = sm + 40960;
    char* Vh = sm + 49152;
    char* Vl = sm + 57344;
    uint32_t uQh = (uint32_t)__cvta_generic_to_shared(Qh);
    uint32_t uQl = uQh + 16384;
    uint32_t uKh = uQh + 32768;
    uint32_t uKl = uQh + 40960;
    uint32_t uVh = uQh + 49152;
    uint32_t uVl = uQh + 57344;

    int tid = threadIdx.x;
    int wid = tid >> 5, lane = tid & 31;
    int g = lane >> 2, t = lane & 3;
    int qb = blockIdx.x;
    int bh = blockIdx.y;
    int b = bh >> 4, h = bh & 15;
    int i0 = qb * 128;
    size_t base = ((size_t)b * SEQ) * DM + h * HD;

    {
        int row = tid >> 1;
        int d0 = (tid & 1) * 32;
        const float* qg = q + base + (size_t)(i0 + row) * DM + d0;
        #pragma unroll
        for (int c = 0; c < 4; ++c) {
            float4 f0 = *(const float4*)(qg + c * 8);
            float4 f1 = *(const float4*)(qg + c * 8 + 4);
            uint4 hh, ll;
            split_pack(f0.x, f0.y, hh.x, ll.x);
            split_pack(f0.z, f0.w, hh.y, ll.y);
            split_pack(f1.x, f1.y, hh.z, ll.z);
            split_pack(f1.z, f1.w, hh.w, ll.w);
            int chunk = (d0 >> 3) + c;
            int off = row * 128 + ((chunk ^ (row & 7)) << 4);
            *(uint4*)(Qh + off) = hh;
            *(uint4*)(Ql + off) = ll;
        }
    }
    __syncthreads();

    int r0 = 16 * wid;
    unsigned aqh[4][4], aql[4][4];
    #pragma unroll
    for (int kc = 0; kc < 4; ++kc) {
        int m = lane >> 3;
        int lr = r0 + (lane & 7) + (m & 1) * 8;
        int lc = (2 * kc + (m >> 1)) ^ (lr & 7);
        ldmx4(aqh[kc], uQh + lr * 128 + lc * 16);
        ldmx4(aql[kc], uQl + lr * 128 + lc * 16);
    }

    float oacc[8][4];
    #pragma unroll
    for (int i = 0; i < 8; ++i)
        #pragma unroll
        for (int c = 0; c < 4; ++c) oacc[i][c] = 0.0f;
    float mrow0 = -1e30f, mrow1 = -1e30f;
    float lrow0 = 0.0f, lrow1 = 0.0f;

    int rowg0 = i0 + r0 + g;
    int ntiles = 2 * qb + 2;
    int nfull  = 2 * qb;

    for (int j = 0; j < ntiles; ++j) {
        __syncthreads();
        {
            int row = tid >> 2;
            int d0 = (tid & 3) * 16;
            const float* kg = k + base + (size_t)(j * 64 + row) * DM + d0;
            const float* vg = v + base + (size_t)(j * 64 + row) * DM + d0;
            #pragma unroll
            for (int c = 0; c < 2; ++c) {
                float4 f0 = *(const float4*)(kg + c * 8);
                float4 f1 = *(const float4*)(kg + c * 8 + 4);
                uint4 hh, ll;
                split_pack(f0.x, f0.y, hh.x, ll.x);
                split_pack(f0.z, f0.w, hh.y, ll.y);
                split_pack(f1.x, f1.y, hh.z, ll.z);
                split_pack(f1.z, f1.w, hh.w, ll.w);
                int chunk = (d0 >> 3) + c;
                int off = row * 128 + ((chunk ^ (row & 7)) << 4);
                *(uint4*)(Kh + off) = hh;
                *(uint4*)(Kl + off) = ll;
                float4 g0 = *(const float4*)(vg + c * 8);
                float4 g1 = *(const float4*)(vg + c * 8 + 4);
                split_pack(g0.x, g0.y, hh.x, ll.x);
                split_pack(g0.z, g0.w, hh.y, ll.y);
                split_pack(g1.x, g1.y, hh.z, ll.z);
                split_pack(g1.z, g1.w, hh.w, ll.w);
                *(uint4*)(Vh + off) = hh;
                *(uint4*)(Vl + off) = ll;
            }
        }
        __syncthreads();

        float sacc[8][4];
        #pragma unroll
        for (int i = 0; i < 8; ++i)
            #pragma unroll
            for (int c = 0; c < 4; ++c) sacc[i][c] = 0.0f;

        #pragma unroll
        for (int nt = 0; nt < 8; nt += 2) {
            #pragma unroll
            for (int p = 0; p < 2; ++p) {
                int lr0 = 8 * nt + (lane & 7);
                int lc0 = (4 * p + (lane >> 3)) ^ (lr0 & 7);
                int lr1 = 8 * (nt + 1) + (lane & 7);
                int lc1 = (4 * p + (lane >> 3)) ^ (lr1 & 7);
                unsigned bkh0[4], bkl0[4], bkh1[4], bkl1[4];
                ldmx4(bkh0, uKh + lr0 * 128 + lc0 * 16);
                ldmx4(bkh1, uKh + lr1 * 128 + lc1 * 16);
                ldmx4(bkl0, uKl + lr0 * 128 + lc0 * 16);
                ldmx4(bkl1, uKl + lr1 * 128 + lc1 * 16);
                mma16(sacc[nt],     aqh[2 * p],     bkh0);
                mma16(sacc[nt + 1], aqh[2 * p],     bkh1);
                mma16(sacc[nt],     aql[2 * p],     bkh0);
                mma16(sacc[nt + 1], aql[2 * p],     bkh1);
                mma16(sacc[nt],     aqh[2 * p],     bkl0);
                mma16(sacc[nt + 1], aqh[2 * p],     bkl1);
                mma16(sacc[nt],     aqh[2 * p + 1], bkh0 + 2);
                mma16(sacc[nt + 1], aqh[2 * p + 1], bkh1 + 2);
                mma16(sacc[nt],     aql[2 * p + 1], bkh0 + 2);
                mma16(sacc[nt + 1], aql[2 * p + 1], bkh1 + 2);
                mma16(sacc[nt],     aqh[2 * p + 1], bkl0 + 2);
                mma16(sacc[nt + 1], aqh[2 * p + 1], bkl1 + 2);
            }
        }

        bool masked = (j >= nfull);
        int jb = j * 64;
        #pragma unroll
        for (int nt = 0; nt < 8; ++nt) {
            #pragma unroll
            for (int c = 0; c < 4; ++c) {
                float val = sacc[nt][c] * 0.125f;
                if (masked) {
                    int col = jb + 8 * nt + 2 * t + (c & 1);
                    int row = rowg0 + ((c >> 1) << 3);
                    if (col > row) val = -1e30f;
                }
                sacc[nt][c] = val;
            }
        }

        float m0 = -1e30f, m1 = -1e30f;
        #pragma unroll
        for (int nt = 0; nt < 8; ++nt) {
            m0 = fmaxf(m0, fmaxf(sacc[nt][0], sacc[nt][1]));
            m1 = fmaxf(m1, fmaxf(sacc[nt][2], sacc[nt][3]));
        }
        m0 = fmaxf(m0, __shfl_xor_sync(0xffffffffu, m0, 1));
        m0 = fmaxf(m0, __shfl_xor_sync(0xffffffffu, m0, 2));
        m1 = fmaxf(m1, __shfl_xor_sync(0xffffffffu, m1, 1));
        m1 = fmaxf(m1, __shfl_xor_sync(0xffffffffu, m1, 2));
        float mn0 = fmaxf(mrow0, m0);
        float mn1 = fmaxf(mrow1, m1);
        float corr0 = __expf(mrow0 - mn0);
        float corr1 = __expf(mrow1 - mn1);
        mrow0 = mn0; mrow1 = mn1;

        unsigned ph01[8], pl01[8], ph23[8], pl23[8];
        float rs0 = 0.0f, rs1 = 0.0f;
        #pragma unroll
        for (int nt = 0; nt < 8; ++nt) {
            float p0 = __expf(sacc[nt][0] - mn0);
            float p1 = __expf(sacc[nt][1] - mn0);
            float p2 = __expf(sacc[nt][2] - mn1);
            float p3 = __expf(sacc[nt][3] - mn1);
            rs0 += p0 + p1;
            rs1 += p2 + p3;
            split_pack(p0, p1, ph01[nt], pl01[nt]);
            split_pack(p2, p3, ph23[nt], pl23[nt]);
        }
        rs0 += __shfl_xor_sync(0xffffffffu, rs0, 1);
        rs0 += __shfl_xor_sync(0xffffffffu, rs0, 2);
        rs1 += __shfl_xor_sync(0xffffffffu, rs1, 1);
        rs1 += __shfl_xor_sync(0xffffffffu, rs1, 2);
        lrow0 = lrow0 * corr0 + rs0;
        lrow1 = lrow1 * corr1 + rs1;
        #pragma unroll
        for (int nd = 0; nd < 8; ++nd) {
            oacc[nd][0] *= corr0; oacc[nd][1] *= corr0;
            oacc[nd][2] *= corr1; oacc[nd][3] *= corr1;
        }

        #pragma unroll
        for (int kc = 0; kc < 4; ++kc) {
            unsigned pah[4] = { ph01[2 * kc], ph23[2 * kc],
                                ph01[2 * kc + 1], ph23[2 * kc + 1] };
            unsigned pal[4] = { pl01[2 * kc], pl23[2 * kc],
                                pl01[2 * kc + 1], pl23[2 * kc + 1] };
            #pragma unroll
            for (int nd2 = 0; nd2 < 4; ++nd2) {
                int lr = 16 * kc + (lane & 15);
                int lc = (2 * nd2 + (lane >> 4)) ^ (lr & 7);
                unsigned bvh[4], bvl[4];
                ldmx4t(bvh, uVh + lr * 128 + lc * 16);
                ldmx4t(bvl, uVl + lr * 128 + lc * 16);
                mma16(oacc[2 * nd2],     pah, bvh);
                mma16(oacc[2 * nd2 + 1], pah, bvh + 2);
                mma16(oacc[2 * nd2],     pal, bvh);
                mma16(oacc[2 * nd2 + 1], pal, bvh + 2);
                mma16(oacc[2 * nd2],     pah, bvl);
                mma16(oacc[2 * nd2 + 1], pah, bvl + 2);
            }
        }
    }

    float inv0 = 1.0f / lrow0;
    float inv1 = 1.0f / lrow1;
    #pragma unroll
    for (int nd = 0; nd < 8; ++nd) {
        int col = 8 * nd + 2 * t;
        size_t off0 = base + (size_t)(rowg0) * DM + col;
        size_t off1 = base + (size_t)(rowg0 + 8) * DM + col;
        unsigned hw, lw;
        split_pack_h(oacc[nd][0] * inv0, oacc[nd][1] * inv0, hw, lw);
        *(unsigned*)(aoh + off0) = hw;
        *(unsigned*)(aol + off0) = lw;
        split_pack_h(oacc[nd][2] * inv1, oacc[nd][3] * inv1, hw, lw);
        *(unsigned*)(aoh + off1) = hw;
        *(unsigned*)(aol + off1) = lw;
    }
}

// ---------------------------------------------------------------------------
// Launch
// ---------------------------------------------------------------------------
extern "C" void kernel_launch(void* const* d_in, const int* in_sizes, int n_in,
                              void* d_out, int out_size) {
    const float* x     = (const float*)d_in[0];
    const float* wq    = (const float*)d_in[1];
    const float* wk    = (const float*)d_in[2];
    const float* wv    = (const float*)d_in[3];
    const float* wo    = (const float*)d_in[4];
    const float* ln1w  = (const float*)d_in[5];
    const float* ln2w  = (const float*)d_in[6];
    const float* upw   = (const float*)d_in[7];
    const float* gatew = (const float*)d_in[8];
    const float* downw = (const float*)d_in[9];
    float* out = (float*)d_out;

    float *q, *k, *v, *x1, *gate;
    cudaGetSymbolAddress((void**)&q,    g_q);
    cudaGetSymbolAddress((void**)&k,    g_k);
    cudaGetSymbolAddress((void**)&v,    g_v);
    cudaGetSymbolAddress((void**)&x1,   g_x1);
    cudaGetSymbolAddress((void**)&gate, g_gate);

    f16 *xnh, *xnl, *aoh, *aol, *hh, *hl;
    f16 *wq16, *wk16, *wv16, *wo16, *up16, *gw16, *dw16;
    cudaGetSymbolAddress((void**)&xnh,  g_xnh);
    cudaGetSymbolAddress((void**)&xnl,  g_xnl);
    cudaGetSymbolAddress((void**)&aoh,  g_aoh);
    cudaGetSymbolAddress((void**)&aol,  g_aol);
    cudaGetSymbolAddress((void**)&hh,   g_hh);
    cudaGetSymbolAddress((void**)&hl,   g_hl);
    cudaGetSymbolAddress((void**)&wq16, g_wq16);
    cudaGetSymbolAddress((void**)&wk16, g_wk16);
    cudaGetSymbolAddress((void**)&wv16, g_wv16);
    cudaGetSymbolAddress((void**)&wo16, g_wo16);
    cudaGetSymbolAddress((void**)&up16, g_up16);
    cudaGetSymbolAddress((void**)&gw16, g_gw16);
    cudaGetSymbolAddress((void**)&dw16, g_dw16);

    cudaFuncSetAttribute(flash_kernel,
                         cudaFuncAttributeMaxDynamicSharedMemorySize, 65536);
    cudaFuncSetAttribute(hgemm_kernel<0>,
                         cudaFuncAttributeMaxDynamicSharedMemorySize, 49152);
    cudaFuncSetAttribute(hgemm_kernel<1>,
                         cudaFuncAttributeMaxDynamicSharedMemorySize, 49152);
    cudaFuncSetAttribute(hgemm_kernel<2>,
                         cudaFuncAttributeMaxDynamicSharedMemorySize, 49152);

    dim3 g1(DM / 128, M_ROWS / 128);    // (8, 64)
    dim3 g2(DFF / 128, M_ROWS / 128);   // (32, 64)

    // Weight conversions to fp16 (single term)
    cvt16_kernel<<<DM * DM / 1024, 256>>>(wq, wq16);
    cvt16_kernel<<<DM * DM / 1024, 256>>>(wk, wk16);
    cvt16_kernel<<<DM * DM / 1024, 256>>>(wv, wv16);
    cvt16_kernel<<<DM * DM / 1024, 256>>>(wo, wo16);
    cvt16_kernel<<<DFF * DM / 1024, 256>>>(upw, up16);
    cvt16_kernel<<<DFF * DM / 1024, 256>>>(gatew, gw16);
    cvt16_kernel<<<DM * DFF / 1024, 256>>>(downw, dw16);

    // ln1 -> split xn (fp16 2-term)
    rmsnorm_split_kernel<<<M_ROWS, 256>>>(x, ln1w, xnh, xnl);
    // q, k, v projections
    hgemm_kernel<0><<<g1, 256, 49152>>>(xnh, xnl, wq16, q, nullptr, nullptr, nullptr, DM, DM);
    hgemm_kernel<0><<<g1, 256, 49152>>>(xnh, xnl, wk16, k, nullptr, nullptr, nullptr, DM, DM);
    hgemm_kernel<0><<<g1, 256, 49152>>>(xnh, xnl, wv16, v, nullptr, nullptr, nullptr, DM, DM);
    rope_kernel<<<(M_ROWS * 512) / 256, 256>>>(q, k);
    // tensor-core flash attention (writes fp16 split ao directly)
    flash_kernel<<<dim3(SEQ / 128, B_SZ * NHEAD), 256, 65536>>>(q, k, v, aoh, aol);
    // o projection + residual
    hgemm_kernel<1><<<g1, 256, 49152>>>(aoh, aol, wo16, x1, nullptr, nullptr, x, DM, DM);
    // ln2 -> split
    rmsnorm_split_kernel<<<M_ROWS, 256>>>(x1, ln2w, xnh, xnl);
    // FFN
    hgemm_kernel<0><<<g2, 256, 49152>>>(xnh, xnl, gw16, gate, nullptr, nullptr, nullptr, DFF, DM);
    hgemm_kernel<2><<<g2, 256, 49152>>>(xnh, xnl, up16, nullptr, hh, hl, gate, DFF, DM);
    hgemm_kernel<1><<<g1, 256, 49152>>>(hh, hl, dw16, out, nullptr, nullptr, x1, DM, DFF);
}

// round 13
// speedup vs baseline: 1.7065x; 1.3292x over previous
#include <cuda_runtime.h>
#include <cuda_bf16.h>
#include <cuda_fp16.h>
#include <math.h>
#include <stdint.h>

// Problem constants
#define B_SZ 4
#define SEQ 2048
#define DM 1024
#define NHEAD 16
#define HD 64
#define DFF 4096
#define M_ROWS (B_SZ * SEQ)   // 8192

typedef __nv_bfloat16 bf16;
typedef __half f16;

// ---------------------------------------------------------------------------
// Scratch buffers
// ---------------------------------------------------------------------------
__device__ float g_q[M_ROWS * DM];
__device__ float g_k[M_ROWS * DM];
__device__ float g_v[M_ROWS * DM];
__device__ float g_x1[M_ROWS * DM];
__device__ float g_gate[M_ROWS * DFF];

__device__ f16 g_xn16[M_ROWS * DM];
__device__ f16 g_ao16[M_ROWS * DM];
__device__ f16 g_h16[M_ROWS * DFF];

__device__ f16 g_wq16[DM * DM];
__device__ f16 g_wk16[DM * DM];
__device__ f16 g_wv16[DM * DM];
__device__ f16 g_wo16[DM * DM];
__device__ f16 g_up16[DFF * DM];
__device__ f16 g_gw16[DFF * DM];
__device__ f16 g_dw16[DM * DFF];

// bf16 pack (flash internal staging)
__device__ __forceinline__ void split_pack(float f0, float f1,
                                           unsigned& h, unsigned& l) {
    bf16 h0 = __float2bfloat16(f0), h1 = __float2bfloat16(f1);
    unsigned short u0 = *(unsigned short*)&h0, u1 = *(unsigned short*)&h1;
    h = ((unsigned)u1 << 16) | u0;
    bf16 l0 = __float2bfloat16(f0 - __bfloat162float(h0));
    bf16 l1 = __float2bfloat16(f1 - __bfloat162float(h1));
    unsigned short v0 = *(unsigned short*)&l0, v1 = *(unsigned short*)&l1;
    l = ((unsigned)v1 << 16) | v0;
}

// ---------------------------------------------------------------------------
// Elementwise kernels
// ---------------------------------------------------------------------------
__global__ __launch_bounds__(256)
void cvt16_kernel(const float* __restrict__ src, f16* __restrict__ dst) {
    size_t i = ((size_t)blockIdx.x * 256 + threadIdx.x) * 4;
    float4 v = *(const float4*)(src + i);
    *(__half2*)(dst + i)     = __floats2half2_rn(v.x, v.y);
    *(__half2*)(dst + i + 2) = __floats2half2_rn(v.z, v.w);
}

__global__ __launch_bounds__(256)
void rmsnorm16_kernel(const float* __restrict__ x,
                      const float* __restrict__ w,
                      f16* __restrict__ y) {
    int row = blockIdx.x;
    int tid = threadIdx.x;
    const float* xr = x + (size_t)row * DM;
    float4 v = *(const float4*)(xr + tid * 4);
    float s = v.x * v.x + v.y * v.y + v.z * v.z + v.w * v.w;
    #pragma unroll
    for (int off = 16; off; off >>= 1)
        s += __shfl_xor_sync(0xffffffffu, s, off);
    __shared__ float red[8];
    if ((tid & 31) == 0) red[tid >> 5] = s;
    __syncthreads();
    float tot = red[0] + red[1] + red[2] + red[3] +
                red[4] + red[5] + red[6] + red[7];
    float inv = rsqrtf(tot * (1.0f / DM) + 1e-5f);
    float4 wv = *(const float4*)(w + tid * 4);
    size_t o = (size_t)row * DM + tid * 4;
    *(__half2*)(&((f16*)y)[o])     = __floats2half2_rn(v.x * inv * wv.x,
                                                       v.y * inv * wv.y);
    *(__half2*)(&((f16*)y)[o + 2]) = __floats2half2_rn(v.z * inv * wv.z,
                                                       v.w * inv * wv.w);
}

__global__ __launch_bounds__(256)
void rope_kernel(float* __restrict__ q, float* __restrict__ k) {
    int idx = blockIdx.x * blockDim.x + threadIdx.x;
    if (idx >= M_ROWS * 512) return;
    int m  = idx >> 9;
    int pir = idx & 511;
    int h  = pir >> 5;
    int pp = pir & 31;
    int s  = m & (SEQ - 1);
    float inv_freq = expf(-(float)(2 * pp) * (9.210340371976184f / 64.0f));
    float ang = (float)s * inv_freq;
    float sn, cs;
    sincosf(ang, &sn, &cs);
    size_t off = (size_t)m * DM + h * HD + 2 * pp;
    float qe = q[off], qo = q[off + 1];
    q[off]     = qe * cs - qo * sn;
    q[off + 1] = qo * cs + qe * sn;
    float ke = k[off], ko = k[off + 1];
    k[off]     = ke * cs - ko * sn;
    k[off + 1] = ko * cs + ke * sn;
}

// ---------------------------------------------------------------------------
// mma / ldmatrix / cp.async primitives
// ---------------------------------------------------------------------------
__device__ __forceinline__ void mma16(float* d, const unsigned* a,
                                      const unsigned* b) {
    asm volatile(
        "mma.sync.aligned.m16n8k16.row.col.f32.bf16.bf16.f32 "
        "{%0,%1,%2,%3}, {%4,%5,%6,%7}, {%8,%9}, {%0,%1,%2,%3};"
        : "+f"(d[0]), "+f"(d[1]), "+f"(d[2]), "+f"(d[3])
        : "r"(a[0]), "r"(a[1]), "r"(a[2]), "r"(a[3]), "r"(b[0]), "r"(b[1]));
}
__device__ __forceinline__ void mma16h(float* d, const unsigned* a,
                                       const unsigned* b) {
    asm volatile(
        "mma.sync.aligned.m16n8k16.row.col.f32.f16.f16.f32 "
        "{%0,%1,%2,%3}, {%4,%5,%6,%7}, {%8,%9}, {%0,%1,%2,%3};"
        : "+f"(d[0]), "+f"(d[1]), "+f"(d[2]), "+f"(d[3])
        : "r"(a[0]), "r"(a[1]), "r"(a[2]), "r"(a[3]), "r"(b[0]), "r"(b[1]));
}
__device__ __forceinline__ void ldmx4(unsigned* r, uint32_t addr) {
    asm volatile(
        "ldmatrix.sync.aligned.m8n8.x4.shared.b16 {%0,%1,%2,%3}, [%4];"
        : "=r"(r[0]), "=r"(r[1]), "=r"(r[2]), "=r"(r[3]) : "r"(addr));
}
__device__ __forceinline__ void ldmx4t(unsigned* r, uint32_t addr) {
    asm volatile(
        "ldmatrix.sync.aligned.m8n8.x4.trans.shared.b16 {%0,%1,%2,%3}, [%4];"
        : "=r"(r[0]), "=r"(r[1]), "=r"(r[2]), "=r"(r[3]) : "r"(addr));
}
__device__ __forceinline__ void cp_async16(uint32_t s, const void* g) {
    asm volatile("cp.async.cg.shared.global [%0], [%1], 16;\n"
                 :: "r"(s), "l"(g));
}
__device__ __forceinline__ void cp_commit() {
    asm volatile("cp.async.commit_group;\n");
}
__device__ __forceinline__ void cp_wait0() {
    asm volatile("cp.async.wait_group 0;\n");
}

// ---------------------------------------------------------------------------
// fp16 1-term GEMM: C[M,N] = A16[M,K] * W16[N,K]^T (+epilogue)
// 128x128x32 tile, 256 thr (8 warps 2x4, 64x32 warp tile), mma.m16n8k16.
// Smem/stage: A 8KB | W 8KB = 16KB; double buffered = 32KB.
// Row: 32 f16 = 64B = 4 chunks of 16B, chunk' = chunk ^ ((row>>1)&3).
// EPI: 0 C=AB; 1 C=AB+aux; 2 C16=half(silu(AB)*aux)
// ---------------------------------------------------------------------------
template <int EPI>
__global__ __launch_bounds__(256, 1)
void hgemm_kernel(const f16* __restrict__ A, const f16* __restrict__ W,
                  float* __restrict__ C, f16* __restrict__ C16,
                  const float* __restrict__ aux, int N, int K) {
    extern __shared__ char smc[];
    int tid = threadIdx.x;
    int wid = tid >> 5, lane = tid & 31;
    int g = lane >> 2, t = lane & 3;
    int wm = wid >> 2, wn = wid & 3;
    int m0 = blockIdx.y * 128;
    int n0 = blockIdx.x * 128;

    uint32_t smem_base = (uint32_t)__cvta_generic_to_shared(smc);

    int mm = lane >> 3;
    int aRowLoc = (mm & 1) * 8 + (lane & 7);
    int aCb = mm >> 1;
    int bRowLoc = (mm >> 1) * 8 + (lane & 7);
    int bCb = mm & 1;

    uint32_t aOff[4]; int aSw[4];
    #pragma unroll
    for (int mt = 0; mt < 4; ++mt) {
        int r = wm * 64 + mt * 16 + aRowLoc;
        aOff[mt] = r * 64;
        aSw[mt] = (r >> 1) & 3;
    }
    uint32_t bOff[2]; int bSw[2];
    #pragma unroll
    for (int nt2 = 0; nt2 < 2; ++nt2) {
        int r = wn * 32 + nt2 * 16 + bRowLoc;
        bOff[nt2] = r * 64;
        bSw[nt2] = (r >> 1) & 3;
    }

    float acc[4][4][4];
    #pragma unroll
    for (int i = 0; i < 4; ++i)
        #pragma unroll
        for (int j = 0; j < 4; ++j)
            #pragma unroll
            for (int c = 0; c < 4; ++c) acc[i][j][c] = 0.0f;

    int niter = K >> 5;
    int grow = tid >> 1;
    int gch0 = (tid & 1) << 1;

    #define STAGE(buf, k0)                                                      \
    {                                                                           \
        _Pragma("unroll")                                                       \
        for (int cc = 0; cc < 2; ++cc) {                                        \
            int ch = gch0 + cc;                                                 \
            uint32_t soff = (uint32_t)(grow * 64 +                              \
                ((ch ^ ((grow >> 1) & 3)) << 4));                               \
            size_t ga = (size_t)(m0 + grow) * K + (k0) + ch * 8;                \
            size_t gb = (size_t)(n0 + grow) * K + (k0) + ch * 8;                \
            uint32_t sb = smem_base + (buf) * 16384 + soff;                     \
            cp_async16(sb,        A + ga);                                      \
            cp_async16(sb + 8192, W + gb);                                      \
        }                                                                       \
        cp_commit();                                                            \
    }

    STAGE(0, 0);
    cp_wait0();
    __syncthreads();

    int buf = 0;
    for (int it = 0; it < niter; ++it) {
        if (it + 1 < niter) STAGE(buf ^ 1, (it + 1) << 5);

        uint32_t tA = smem_base + buf * 16384;
        uint32_t tB = tA + 8192;

        #pragma unroll
        for (int ck = 0; ck < 2; ++ck) {
            unsigned bf[2][4];
            #pragma unroll
            for (int nt2 = 0; nt2 < 2; ++nt2) {
                uint32_t off = bOff[nt2] +
                               (((2 * ck + bCb) ^ bSw[nt2]) << 4);
                ldmx4(bf[nt2], tB + off);
            }
            #pragma unroll
            for (int mp = 0; mp < 2; ++mp) {
                int mt0 = 2 * mp, mt1 = 2 * mp + 1;
                uint32_t off0 = aOff[mt0] + (((2 * ck + aCb) ^ aSw[mt0]) << 4);
                uint32_t off1 = aOff[mt1] + (((2 * ck + aCb) ^ aSw[mt1]) << 4);
                unsigned a0[4], a1[4];
                ldmx4(a0, tA + off0);
                ldmx4(a1, tA + off1);
                mma16h(acc[mt0][0], a0, bf[0]);
                mma16h(acc[mt0][1], a0, bf[0] + 2);
                mma16h(acc[mt0][2], a0, bf[1]);
                mma16h(acc[mt0][3], a0, bf[1] + 2);
                mma16h(acc[mt1][0], a1, bf[0]);
                mma16h(acc[mt1][1], a1, bf[0] + 2);
                mma16h(acc[mt1][2], a1, bf[1]);
                mma16h(acc[mt1][3], a1, bf[1] + 2);
            }
        }

        if (it + 1 < niter) cp_wait0();
        __syncthreads();
        buf ^= 1;
    }
    #undef STAGE

    #pragma unroll
    for (int mt = 0; mt < 4; ++mt) {
        #pragma unroll
        for (int nt = 0; nt < 4; ++nt) {
            int rb = m0 + wm * 64 + mt * 16 + g;
            int cb = n0 + wn * 32 + nt * 8 + 2 * t;
            #pragma unroll
            for (int half = 0; half < 2; ++half) {
                size_t off = (size_t)(rb + half * 8) * N + cb;
                #pragma unroll
                for (int e = 0; e < 2; ++e) {
                    float u = acc[mt][nt][half * 2 + e];
                    if (EPI == 0) {
                        C[off + e] = u;
                    } else if (EPI == 1) {
                        C[off + e] = u + aux[off + e];
                    } else {
                        float sg = 1.0f / (1.0f + __expf(-u));
                        C16[off + e] = __float2half_rn(u * sg * aux[off + e]);
                    }
                }
            }
        }
    }
}

// ---------------------------------------------------------------------------
// Tensor-core flash attention (causal), bf16 split-compensated internals,
// single fp16 output (consumed by the 1-term wo GEMM).
// ---------------------------------------------------------------------------
__global__ __launch_bounds__(256, 1)
void flash_kernel(const float* __restrict__ q, const float* __restrict__ k,
                  const float* __restrict__ v, f16* __restrict__ ao) {
    extern __shared__ char sm[];
    char* Qh = sm;
    char* Ql = sm + 16384;
    char* Kh = sm + 32768;
    char* Kl = sm + 40960;
    char* Vh = sm + 49152;
    char* Vl = sm + 57344;
    uint32_t uQh = (uint32_t)__cvta_generic_to_shared(Qh);
    uint32_t uQl = uQh + 16384;
    uint32_t uKh = uQh + 32768;
    uint32_t uKl = uQh + 40960;
    uint32_t uVh = uQh + 49152;
    uint32_t uVl = uQh + 57344;

    int tid = threadIdx.x;
    int wid = tid >> 5, lane = tid & 31;
    int g = lane >> 2, t = lane & 3;
    int qb = blockIdx.x;
    int bh = blockIdx.y;
    int b = bh >> 4, h = bh & 15;
    int i0 = qb * 128;
    size_t base = ((size_t)b * SEQ) * DM + h * HD;

    {
        int row = tid >> 1;
        int d0 = (tid & 1) * 32;
        const float* qg = q + base + (size_t)(i0 + row) * DM + d0;
        #pragma unroll
        for (int c = 0; c < 4; ++c) {
            float4 f0 = *(const float4*)(qg + c * 8);
            float4 f1 = *(const float4*)(qg + c * 8 + 4);
            uint4 hh, ll;
            split_pack(f0.x, f0.y, hh.x, ll.x);
            split_pack(f0.z, f0.w, hh.y, ll.y);
            split_pack(f1.x, f1.y, hh.z, ll.z);
            split_pack(f1.z, f1.w, hh.w, ll.w);
            int chunk = (d0 >> 3) + c;
            int off = row * 128 + ((chunk ^ (row & 7)) << 4);
            *(uint4*)(Qh + off) = hh;
            *(uint4*)(Ql + off) = ll;
        }
    }
    __syncthreads();

    int r0 = 16 * wid;
    unsigned aqh[4][4], aql[4][4];
    #pragma unroll
    for (int kc = 0; kc < 4; ++kc) {
        int m = lane >> 3;
        int lr = r0 + (lane & 7) + (m & 1) * 8;
        int lc = (2 * kc + (m >> 1)) ^ (lr & 7);
        ldmx4(aqh[kc], uQh + lr * 128 + lc * 16);
        ldmx4(aql[kc], uQl + lr * 128 + lc * 16);
    }

    float oacc[8][4];
    #pragma unroll
    for (int i = 0; i < 8; ++i)
        #pragma unroll
        for (int c = 0; c < 4; ++c) oacc[i][c] = 0.0f;
    float mrow0 = -1e30f, mrow1 = -1e30f;
    float lrow0 = 0.0f, lrow1 = 0.0f;

    int rowg0 = i0 + r0 + g;
    int ntiles = 2 * qb + 2;
    int nfull  = 2 * qb;

    for (int j = 0; j < ntiles; ++j) {
        __syncthreads();
        {
            int row = tid >> 2;
            int d0 = (tid & 3) * 16;
            const float* kg = k + base + (size_t)(j * 64 + row) * DM + d0;
            const float* vg = v + base + (size_t)(j * 64 + row) * DM + d0;
            #pragma unroll
            for (int c = 0; c < 2; ++c) {
                float4 f0 = *(const float4*)(kg + c * 8);
                float4 f1 = *(const float4*)(kg + c * 8 + 4);
                uint4 hh, ll;
                split_pack(f0.x, f0.y, hh.x, ll.x);
                split_pack(f0.z, f0.w, hh.y, ll.y);
                split_pack(f1.x, f1.y, hh.z, ll.z);
                split_pack(f1.z, f1.w, hh.w, ll.w);
                int chunk = (d0 >> 3) + c;
                int off = row * 128 + ((chunk ^ (row & 7)) << 4);
                *(uint4*)(Kh + off) = hh;
                *(uint4*)(Kl + off) = ll;
                float4 g0 = *(const float4*)(vg + c * 8);
                float4 g1 = *(const float4*)(vg + c * 8 + 4);
                split_pack(g0.x, g0.y, hh.x, ll.x);
                split_pack(g0.z, g0.w, hh.y, ll.y);
                split_pack(g1.x, g1.y, hh.z, ll.z);
                split_pack(g1.z, g1.w, hh.w, ll.w);
                *(uint4*)(Vh + off) = hh;
                *(uint4*)(Vl + off) = ll;
            }
        }
        __syncthreads();

        float sacc[8][4];
        #pragma unroll
        for (int i = 0; i < 8; ++i)
            #pragma unroll
            for (int c = 0; c < 4; ++c) sacc[i][c] = 0.0f;

        #pragma unroll
        for (int nt = 0; nt < 8; nt += 2) {
            #pragma unroll
            for (int p = 0; p < 2; ++p) {
                int lr0 = 8 * nt + (lane & 7);
                int lc0 = (4 * p + (lane >> 3)) ^ (lr0 & 7);
                int lr1 = 8 * (nt + 1) + (lane & 7);
                int lc1 = (4 * p + (lane >> 3)) ^ (lr1 & 7);
                unsigned bkh0[4], bkl0[4], bkh1[4], bkl1[4];
                ldmx4(bkh0, uKh + lr0 * 128 + lc0 * 16);
                ldmx4(bkh1, uKh + lr1 * 128 + lc1 * 16);
                ldmx4(bkl0, uKl + lr0 * 128 + lc0 * 16);
                ldmx4(bkl1, uKl + lr1 * 128 + lc1 * 16);
                mma16(sacc[nt],     aqh[2 * p],     bkh0);
                mma16(sacc[nt + 1], aqh[2 * p],     bkh1);
                mma16(sacc[nt],     aql[2 * p],     bkh0);
                mma16(sacc[nt + 1], aql[2 * p],     bkh1);
                mma16(sacc[nt],     aqh[2 * p],     bkl0);
                mma16(sacc[nt + 1], aqh[2 * p],     bkl1);
                mma16(sacc[nt],     aqh[2 * p + 1], bkh0 + 2);
                mma16(sacc[nt + 1], aqh[2 * p + 1], bkh1 + 2);
                mma16(sacc[nt],     aql[2 * p + 1], bkh0 + 2);
                mma16(sacc[nt + 1], aql[2 * p + 1], bkh1 + 2);
                mma16(sacc[nt],     aqh[2 * p + 1], bkl0 + 2);
                mma16(sacc[nt + 1], aqh[2 * p + 1], bkl1 + 2);
            }
        }

        bool masked = (j >= nfull);
        int jb = j * 64;
        #pragma unroll
        for (int nt = 0; nt < 8; ++nt) {
            #pragma unroll
            for (int c = 0; c < 4; ++c) {
                float val = sacc[nt][c] * 0.125f;
                if (masked) {
                    int col = jb + 8 * nt + 2 * t + (c & 1);
                    int row = rowg0 + ((c >> 1) << 3);
                    if (col > row) val = -1e30f;
                }
                sacc[nt][c] = val;
            }
        }

        float m0 = -1e30f, m1 = -1e30f;
        #pragma unroll
        for (int nt = 0; nt < 8; ++nt) {
            m0 = fmaxf(m0, fmaxf(sacc[nt][0], sacc[nt][1]));
            m1 = fmaxf(m1, fmaxf(sacc[nt][2], sacc[nt][3]));
        }
        m0 = fmaxf(m0, __shfl_xor_sync(0xffffffffu, m0, 1));
        m0 = fmaxf(m0, __shfl_xor_sync(0xffffffffu, m0, 2));
        m1 = fmaxf(m1, __shfl_xor_sync(0xffffffffu, m1, 1));
        m1 = fmaxf(m1, __shfl_xor_sync(0xffffffffu, m1, 2));
        float mn0 = fmaxf(mrow0, m0);
        float mn1 = fmaxf(mrow1, m1);
        float corr0 = __expf(mrow0 - mn0);
        float corr1 = __expf(mrow1 - mn1);
        mrow0 = mn0; mrow1 = mn1;

        unsigned ph01[8], pl01[8], ph23[8], pl23[8];
        float rs0 = 0.0f, rs1 = 0.0f;
        #pragma unroll
        for (int nt = 0; nt < 8; ++nt) {
            float p0 = __expf(sacc[nt][0] - mn0);
            float p1 = __expf(sacc[nt][1] - mn0);
            float p2 = __expf(sacc[nt][2] - mn1);
            float p3 = __expf(sacc[nt][3] - mn1);
            rs0 += p0 + p1;
            rs1 += p2 + p3;
            split_pack(p0, p1, ph01[nt], pl01[nt]);
            split_pack(p2, p3, ph23[nt], pl23[nt]);
        }
        rs0 += __shfl_xor_sync(0xffffffffu, rs0, 1);
        rs0 += __shfl_xor_sync(0xffffffffu, rs0, 2);
        rs1 += __shfl_xor_sync(0xffffffffu, rs1, 1);
        rs1 += __shfl_xor_sync(0xffffffffu, rs1, 2);
        lrow0 = lrow0 * corr0 + rs0;
        lrow1 = lrow1 * corr1 + rs1;
        #pragma unroll
        for (int nd = 0; nd < 8; ++nd) {
            oacc[nd][0] *= corr0; oacc[nd][1] *= corr0;
            oacc[nd][2] *= corr1; oacc[nd][3] *= corr1;
        }

        #pragma unroll
        for (int kc = 0; kc < 4; ++kc) {
            unsigned pah[4] = { ph01[2 * kc], ph23[2 * kc],
                                ph01[2 * kc + 1], ph23[2 * kc + 1] };
            unsigned pal[4] = { pl01[2 * kc], pl23[2 * kc],
                                pl01[2 * kc + 1], pl23[2 * kc + 1] };
            #pragma unroll
            for (int nd2 = 0; nd2 < 4; ++nd2) {
                int lr = 16 * kc + (lane & 15);
                int lc = (2 * nd2 + (lane >> 4)) ^ (lr & 7);
                unsigned bvh[4], bvl[4];
                ldmx4t(bvh, uVh + lr * 128 + lc * 16);
                ldmx4t(bvl, uVl + lr * 128 + lc * 16);
                mma16(oacc[2 * nd2],     pah, bvh);
                mma16(oacc[2 * nd2 + 1], pah, bvh + 2);
                mma16(oacc[2 * nd2],     pal, bvh);
                mma16(oacc[2 * nd2 + 1], pal, bvh + 2);
                mma16(oacc[2 * nd2],     pah, bvl);
                mma16(oacc[2 * nd2 + 1], pah, bvl + 2);
            }
        }
    }

    float inv0 = 1.0f / lrow0;
    float inv1 = 1.0f / lrow1;
    #pragma unroll
    for (int nd = 0; nd < 8; ++nd) {
        int col = 8 * nd + 2 * t;
        size_t off0 = base + (size_t)(rowg0) * DM + col;
        size_t off1 = base + (size_t)(rowg0 + 8) * DM + col;
        *(__half2*)(ao + off0) = __floats2half2_rn(oacc[nd][0] * inv0,
                                                   oacc[nd][1] * inv0);
        *(__half2*)(ao + off1) = __floats2half2_rn(oacc[nd][2] * inv1,
                                                   oacc[nd][3] * inv1);
    }
}

// ---------------------------------------------------------------------------
// Launch
// ---------------------------------------------------------------------------
extern "C" void kernel_launch(void* const* d_in, const int* in_sizes, int n_in,
                              void* d_out, int out_size) {
    const float* x     = (const float*)d_in[0];
    const float* wq    = (const float*)d_in[1];
    const float* wk    = (const float*)d_in[2];
    const float* wv    = (const float*)d_in[3];
    const float* wo    = (const float*)d_in[4];
    const float* ln1w  = (const float*)d_in[5];
    const float* ln2w  = (const float*)d_in[6];
    const float* upw   = (const float*)d_in[7];
    const float* gatew = (const float*)d_in[8];
    const float* downw = (const float*)d_in[9];
    float* out = (float*)d_out;

    float *q, *k, *v, *x1, *gate;
    cudaGetSymbolAddress((void**)&q,    g_q);
    cudaGetSymbolAddress((void**)&k,    g_k);
    cudaGetSymbolAddress((void**)&v,    g_v);
    cudaGetSymbolAddress((void**)&x1,   g_x1);
    cudaGetSymbolAddress((void**)&gate, g_gate);

    f16 *xn16, *ao16, *h16;
    f16 *wq16, *wk16, *wv16, *wo16, *up16, *gw16, *dw16;
    cudaGetSymbolAddress((void**)&xn16, g_xn16);
    cudaGetSymbolAddress((void**)&ao16, g_ao16);
    cudaGetSymbolAddress((void**)&h16,  g_h16);
    cudaGetSymbolAddress((void**)&wq16, g_wq16);
    cudaGetSymbolAddress((void**)&wk16, g_wk16);
    cudaGetSymbolAddress((void**)&wv16, g_wv16);
    cudaGetSymbolAddress((void**)&wo16, g_wo16);
    cudaGetSymbolAddress((void**)&up16, g_up16);
    cudaGetSymbolAddress((void**)&gw16, g_gw16);
    cudaGetSymbolAddress((void**)&dw16, g_dw16);

    cudaFuncSetAttribute(flash_kernel,
                         cudaFuncAttributeMaxDynamicSharedMemorySize, 65536);
    cudaFuncSetAttribute(hgemm_kernel<0>,
                         cudaFuncAttributeMaxDynamicSharedMemorySize, 32768);
    cudaFuncSetAttribute(hgemm_kernel<1>,
                         cudaFuncAttributeMaxDynamicSharedMemorySize, 32768);
    cudaFuncSetAttribute(hgemm_kernel<2>,
                         cudaFuncAttributeMaxDynamicSharedMemorySize, 32768);

    dim3 g1(DM / 128, M_ROWS / 128);    // (8, 64)
    dim3 g2(DFF / 128, M_ROWS / 128);   // (32, 64)

    // Weight conversions to fp16
    cvt16_kernel<<<DM * DM / 1024, 256>>>(wq, wq16);
    cvt16_kernel<<<DM * DM / 1024, 256>>>(wk, wk16);
    cvt16_kernel<<<DM * DM / 1024, 256>>>(wv, wv16);
    cvt16_kernel<<<DM * DM / 1024, 256>>>(wo, wo16);
    cvt16_kernel<<<DFF * DM / 1024, 256>>>(upw, up16);
    cvt16_kernel<<<DFF * DM / 1024, 256>>>(gatew, gw16);
    cvt16_kernel<<<DM * DFF / 1024, 256>>>(downw, dw16);

    // ln1 -> fp16 xn
    rmsnorm16_kernel<<<M_ROWS, 256>>>(x, ln1w, xn16);
    // q, k, v projections (1-term fp16)
    hgemm_kernel<0><<<g1, 256, 32768>>>(xn16, wq16, q, nullptr, nullptr, DM, DM);
    hgemm_kernel<0><<<g1, 256, 32768>>>(xn16, wk16, k, nullptr, nullptr, DM, DM);
    hgemm_kernel<0><<<g1, 256, 32768>>>(xn16, wv16, v, nullptr, nullptr, DM, DM);
    rope_kernel<<<(M_ROWS * 512) / 256, 256>>>(q, k);
    // tensor-core flash attention (fp16 ao output)
    flash_kernel<<<dim3(SEQ / 128, B_SZ * NHEAD), 256, 65536>>>(q, k, v, ao16);
    // o projection + residual
    hgemm_kernel<1><<<g1, 256, 32768>>>(ao16, wo16, x1, nullptr, x, DM, DM);
    // ln2 -> fp16 xn
    rmsnorm16_kernel<<<M_ROWS, 256>>>(x1, ln2w, xn16);
    // FFN
    hgemm_kernel<0><<<g2, 256, 32768>>>(xn16, gw16, gate, nullptr, nullptr, DFF, DM);
    hgemm_kernel<2><<<g2, 256, 32768>>>(xn16, up16, nullptr, h16, gate, DFF, DM);
    hgemm_kernel<1><<<g1, 256, 32768>>>(h16, dw16, out, nullptr, x1, DM, DFF);
}

// round 14
// speedup vs baseline: 1.8231x; 1.0683x over previous
#include <cuda_runtime.h>
#include <cuda_bf16.h>
#include <cuda_fp16.h>
#include <math.h>
#include <stdint.h>

// Problem constants
#define B_SZ 4
#define SEQ 2048
#define DM 1024
#define NHEAD 16
#define HD 64
#define DFF 4096
#define M_ROWS (B_SZ * SEQ)   // 8192

typedef __nv_bfloat16 bf16;
typedef __half f16;

// ---------------------------------------------------------------------------
// Scratch buffers
// ---------------------------------------------------------------------------
__device__ float g_q[M_ROWS * DM];
__device__ float g_k[M_ROWS * DM];
__device__ float g_v[M_ROWS * DM];
__device__ float g_x1[M_ROWS * DM];
__device__ float g_gate[M_ROWS * DFF];

__device__ f16 g_xn16[M_ROWS * DM];
__device__ f16 g_ao16[M_ROWS * DM];
__device__ f16 g_h16[M_ROWS * DFF];

__device__ f16 g_wq16[DM * DM];
__device__ f16 g_wk16[DM * DM];
__device__ f16 g_wv16[DM * DM];
__device__ f16 g_wo16[DM * DM];
__device__ f16 g_up16[DFF * DM];
__device__ f16 g_gw16[DFF * DM];
__device__ f16 g_dw16[DM * DFF];

// bf16 split pack (flash Q/K staging)
__device__ __forceinline__ void split_pack(float f0, float f1,
                                           unsigned& h, unsigned& l) {
    bf16 h0 = __float2bfloat16(f0), h1 = __float2bfloat16(f1);
    unsigned short u0 = *(unsigned short*)&h0, u1 = *(unsigned short*)&h1;
    h = ((unsigned)u1 << 16) | u0;
    bf16 l0 = __float2bfloat16(f0 - __bfloat162float(h0));
    bf16 l1 = __float2bfloat16(f1 - __bfloat162float(h1));
    unsigned short v0 = *(unsigned short*)&l0, v1 = *(unsigned short*)&l1;
    l = ((unsigned)v1 << 16) | v0;
}
// fp16 pair pack
__device__ __forceinline__ unsigned packh2(float a, float b) {
    __half2 h = __floats2half2_rn(a, b);
    return *(unsigned*)&h;
}

// ---------------------------------------------------------------------------
// Elementwise kernels
// ---------------------------------------------------------------------------
__global__ __launch_bounds__(256)
void cvt16_kernel(const float* __restrict__ src, f16* __restrict__ dst) {
    size_t i = ((size_t)blockIdx.x * 256 + threadIdx.x) * 4;
    float4 v = *(const float4*)(src + i);
    *(__half2*)(dst + i)     = __floats2half2_rn(v.x, v.y);
    *(__half2*)(dst + i + 2) = __floats2half2_rn(v.z, v.w);
}

__global__ __launch_bounds__(256)
void rmsnorm16_kernel(const float* __restrict__ x,
                      const float* __restrict__ w,
                      f16* __restrict__ y) {
    int row = blockIdx.x;
    int tid = threadIdx.x;
    const float* xr = x + (size_t)row * DM;
    float4 v = *(const float4*)(xr + tid * 4);
    float s = v.x * v.x + v.y * v.y + v.z * v.z + v.w * v.w;
    #pragma unroll
    for (int off = 16; off; off >>= 1)
        s += __shfl_xor_sync(0xffffffffu, s, off);
    __shared__ float red[8];
    if ((tid & 31) == 0) red[tid >> 5] = s;
    __syncthreads();
    float tot = red[0] + red[1] + red[2] + red[3] +
                red[4] + red[5] + red[6] + red[7];
    float inv = rsqrtf(tot * (1.0f / DM) + 1e-5f);
    float4 wv = *(const float4*)(w + tid * 4);
    size_t o = (size_t)row * DM + tid * 4;
    *(__half2*)(y + o)     = __floats2half2_rn(v.x * inv * wv.x,
                                               v.y * inv * wv.y);
    *(__half2*)(y + o + 2) = __floats2half2_rn(v.z * inv * wv.z,
                                               v.w * inv * wv.w);
}

__global__ __launch_bounds__(256)
void rope_kernel(float* __restrict__ q, float* __restrict__ k) {
    int idx = blockIdx.x * blockDim.x + threadIdx.x;
    if (idx >= M_ROWS * 512) return;
    int m  = idx >> 9;
    int pir = idx & 511;
    int h  = pir >> 5;
    int pp = pir & 31;
    int s  = m & (SEQ - 1);
    float inv_freq = expf(-(float)(2 * pp) * (9.210340371976184f / 64.0f));
    float ang = (float)s * inv_freq;
    float sn, cs;
    sincosf(ang, &sn, &cs);
    size_t off = (size_t)m * DM + h * HD + 2 * pp;
    float qe = q[off], qo = q[off + 1];
    q[off]     = qe * cs - qo * sn;
    q[off + 1] = qo * cs + qe * sn;
    float ke = k[off], ko = k[off + 1];
    k[off]     = ke * cs - ko * sn;
    k[off + 1] = ko * cs + ke * sn;
}

// ---------------------------------------------------------------------------
// mma / ldmatrix / cp.async primitives
// ---------------------------------------------------------------------------
__device__ __forceinline__ void mma16(float* d, const unsigned* a,
                                      const unsigned* b) {
    asm volatile(
        "mma.sync.aligned.m16n8k16.row.col.f32.bf16.bf16.f32 "
        "{%0,%1,%2,%3}, {%4,%5,%6,%7}, {%8,%9}, {%0,%1,%2,%3};"
        : "+f"(d[0]), "+f"(d[1]), "+f"(d[2]), "+f"(d[3])
        : "r"(a[0]), "r"(a[1]), "r"(a[2]), "r"(a[3]), "r"(b[0]), "r"(b[1]));
}
__device__ __forceinline__ void mma16h(float* d, const unsigned* a,
                                       const unsigned* b) {
    asm volatile(
        "mma.sync.aligned.m16n8k16.row.col.f32.f16.f16.f32 "
        "{%0,%1,%2,%3}, {%4,%5,%6,%7}, {%8,%9}, {%0,%1,%2,%3};"
        : "+f"(d[0]), "+f"(d[1]), "+f"(d[2]), "+f"(d[3])
        : "r"(a[0]), "r"(a[1]), "r"(a[2]), "r"(a[3]), "r"(b[0]), "r"(b[1]));
}
__device__ __forceinline__ void ldmx4(unsigned* r, uint32_t addr) {
    asm volatile(
        "ldmatrix.sync.aligned.m8n8.x4.shared.b16 {%0,%1,%2,%3}, [%4];"
        : "=r"(r[0]), "=r"(r[1]), "=r"(r[2]), "=r"(r[3]) : "r"(addr));
}
__device__ __forceinline__ void ldmx4t(unsigned* r, uint32_t addr) {
    asm volatile(
        "ldmatrix.sync.aligned.m8n8.x4.trans.shared.b16 {%0,%1,%2,%3}, [%4];"
        : "=r"(r[0]), "=r"(r[1]), "=r"(r[2]), "=r"(r[3]) : "r"(addr));
}
__device__ __forceinline__ void cp_async16(uint32_t s, const void* g) {
    asm volatile("cp.async.cg.shared.global [%0], [%1], 16;\n"
                 :: "r"(s), "l"(g));
}
__device__ __forceinline__ void cp_commit() {
    asm volatile("cp.async.commit_group;\n");
}
__device__ __forceinline__ void cp_wait0() {
    asm volatile("cp.async.wait_group 0;\n");
}

// ---------------------------------------------------------------------------
// fp16 1-term GEMM: C[M,N] = A16[M,K] * W16[N,K]^T (+epilogue)  (round 12)
// ---------------------------------------------------------------------------
template <int EPI>
__global__ __launch_bounds__(256, 1)
void hgemm_kernel(const f16* __restrict__ A, const f16* __restrict__ W,
                  float* __restrict__ C, f16* __restrict__ C16,
                  const float* __restrict__ aux, int N, int K) {
    extern __shared__ char smc[];
    int tid = threadIdx.x;
    int wid = tid >> 5, lane = tid & 31;
    int g = lane >> 2, t = lane & 3;
    int wm = wid >> 2, wn = wid & 3;
    int m0 = blockIdx.y * 128;
    int n0 = blockIdx.x * 128;

    uint32_t smem_base = (uint32_t)__cvta_generic_to_shared(smc);

    int mm = lane >> 3;
    int aRowLoc = (mm & 1) * 8 + (lane & 7);
    int aCb = mm >> 1;
    int bRowLoc = (mm >> 1) * 8 + (lane & 7);
    int bCb = mm & 1;

    uint32_t aOff[4]; int aSw[4];
    #pragma unroll
    for (int mt = 0; mt < 4; ++mt) {
        int r = wm * 64 + mt * 16 + aRowLoc;
        aOff[mt] = r * 64;
        aSw[mt] = (r >> 1) & 3;
    }
    uint32_t bOff[2]; int bSw[2];
    #pragma unroll
    for (int nt2 = 0; nt2 < 2; ++nt2) {
        int r = wn * 32 + nt2 * 16 + bRowLoc;
        bOff[nt2] = r * 64;
        bSw[nt2] = (r >> 1) & 3;
    }

    float acc[4][4][4];
    #pragma unroll
    for (int i = 0; i < 4; ++i)
        #pragma unroll
        for (int j = 0; j < 4; ++j)
            #pragma unroll
            for (int c = 0; c < 4; ++c) acc[i][j][c] = 0.0f;

    int niter = K >> 5;
    int grow = tid >> 1;
    int gch0 = (tid & 1) << 1;

    #define STAGE(buf, k0)                                                      \
    {                                                                           \
        _Pragma("unroll")                                                       \
        for (int cc = 0; cc < 2; ++cc) {                                        \
            int ch = gch0 + cc;                                                 \
            uint32_t soff = (uint32_t)(grow * 64 +                              \
                ((ch ^ ((grow >> 1) & 3)) << 4));                               \
            size_t ga = (size_t)(m0 + grow) * K + (k0) + ch * 8;                \
            size_t gb = (size_t)(n0 + grow) * K + (k0) + ch * 8;                \
            uint32_t sb = smem_base + (buf) * 16384 + soff;                     \
            cp_async16(sb,        A + ga);                                      \
            cp_async16(sb + 8192, W + gb);                                      \
        }                                                                       \
        cp_commit();                                                            \
    }

    STAGE(0, 0);
    cp_wait0();
    __syncthreads();

    int buf = 0;
    for (int it = 0; it < niter; ++it) {
        if (it + 1 < niter) STAGE(buf ^ 1, (it + 1) << 5);

        uint32_t tA = smem_base + buf * 16384;
        uint32_t tB = tA + 8192;

        #pragma unroll
        for (int ck = 0; ck < 2; ++ck) {
            unsigned bf[2][4];
            #pragma unroll
            for (int nt2 = 0; nt2 < 2; ++nt2) {
                uint32_t off = bOff[nt2] +
                               (((2 * ck + bCb) ^ bSw[nt2]) << 4);
                ldmx4(bf[nt2], tB + off);
            }
            #pragma unroll
            for (int mp = 0; mp < 2; ++mp) {
                int mt0 = 2 * mp, mt1 = 2 * mp + 1;
                uint32_t off0 = aOff[mt0] + (((2 * ck + aCb) ^ aSw[mt0]) << 4);
                uint32_t off1 = aOff[mt1] + (((2 * ck + aCb) ^ aSw[mt1]) << 4);
                unsigned a0[4], a1[4];
                ldmx4(a0, tA + off0);
                ldmx4(a1, tA + off1);
                mma16h(acc[mt0][0], a0, bf[0]);
                mma16h(acc[mt0][1], a0, bf[0] + 2);
                mma16h(acc[mt0][2], a0, bf[1]);
                mma16h(acc[mt0][3], a0, bf[1] + 2);
                mma16h(acc[mt1][0], a1, bf[0]);
                mma16h(acc[mt1][1], a1, bf[0] + 2);
                mma16h(acc[mt1][2], a1, bf[1]);
                mma16h(acc[mt1][3], a1, bf[1] + 2);
            }
        }

        if (it + 1 < niter) cp_wait0();
        __syncthreads();
        buf ^= 1;
    }
    #undef STAGE

    #pragma unroll
    for (int mt = 0; mt < 4; ++mt) {
        #pragma unroll
        for (int nt = 0; nt < 4; ++nt) {
            int rb = m0 + wm * 64 + mt * 16 + g;
            int cb = n0 + wn * 32 + nt * 8 + 2 * t;
            #pragma unroll
            for (int half = 0; half < 2; ++half) {
                size_t off = (size_t)(rb + half * 8) * N + cb;
                #pragma unroll
                for (int e = 0; e < 2; ++e) {
                    float u = acc[mt][nt][half * 2 + e];
                    if (EPI == 0) {
                        C[off + e] = u;
                    } else if (EPI == 1) {
                        C[off + e] = u + aux[off + e];
                    } else {
                        float sg = 1.0f / (1.0f + __expf(-u));
                        C16[off + e] = __float2half_rn(u * sg * aux[off + e]);
                    }
                }
            }
        }
    }
}

// ---------------------------------------------------------------------------
// Tensor-core flash attention (causal).
// S = QK^T: bf16 3-term compensated (logit accuracy).
// PV: single fp16 P and V (1 mma per fragment pair).
// smem: Qh 16K | Ql 16K | Kh 8K | Kl 8K | V16 8K = 56KB.
// Output: single fp16 ao.
// ---------------------------------------------------------------------------
__global__ __launch_bounds__(256, 1)
void flash_kernel(const float* __restrict__ q, const float* __restrict__ k,
                  const float* __restrict__ v, f16* __restrict__ ao) {
    extern __shared__ char sm[];
    char* Qh = sm;
    char* Ql = sm + 16384;
    char* Kh = sm + 32768;
    char* Kl = sm + 40960;
    char* V16 = sm + 49152;
    uint32_t uQh = (uint32_t)__cvta_generic_to_shared(Qh);
    uint32_t uQl = uQh + 16384;
    uint32_t uKh = uQh + 32768;
    uint32_t uKl = uQh + 40960;
    uint32_t uV  = uQh + 49152;

    int tid = threadIdx.x;
    int wid = tid >> 5, lane = tid & 31;
    int g = lane >> 2, t = lane & 3;
    int qb = blockIdx.x;
    int bh = blockIdx.y;
    int b = bh >> 4, h = bh & 15;
    int i0 = qb * 128;
    size_t base = ((size_t)b * SEQ) * DM + h * HD;

    // stage Q (fp32 -> bf16 split)
    {
        int row = tid >> 1;
        int d0 = (tid & 1) * 32;
        const float* qg = q + base + (size_t)(i0 + row) * DM + d0;
        #pragma unroll
        for (int c = 0; c < 4; ++c) {
            float4 f0 = *(const float4*)(qg + c * 8);
            float4 f1 = *(const float4*)(qg + c * 8 + 4);
            uint4 hh, ll;
            split_pack(f0.x, f0.y, hh.x, ll.x);
            split_pack(f0.z, f0.w, hh.y, ll.y);
            split_pack(f1.x, f1.y, hh.z, ll.z);
            split_pack(f1.z, f1.w, hh.w, ll.w);
            int chunk = (d0 >> 3) + c;
            int off = row * 128 + ((chunk ^ (row & 7)) << 4);
            *(uint4*)(Qh + off) = hh;
            *(uint4*)(Ql + off) = ll;
        }
    }
    __syncthreads();

    int r0 = 16 * wid;
    unsigned aqh[4][4], aql[4][4];
    #pragma unroll
    for (int kc = 0; kc < 4; ++kc) {
        int m = lane >> 3;
        int lr = r0 + (lane & 7) + (m & 1) * 8;
        int lc = (2 * kc + (m >> 1)) ^ (lr & 7);
        ldmx4(aqh[kc], uQh + lr * 128 + lc * 16);
        ldmx4(aql[kc], uQl + lr * 128 + lc * 16);
    }

    float oacc[8][4];
    #pragma unroll
    for (int i = 0; i < 8; ++i)
        #pragma unroll
        for (int c = 0; c < 4; ++c) oacc[i][c] = 0.0f;
    float mrow0 = -1e30f, mrow1 = -1e30f;
    float lrow0 = 0.0f, lrow1 = 0.0f;

    int rowg0 = i0 + r0 + g;
    int ntiles = 2 * qb + 2;
    int nfull  = 2 * qb;

    for (int j = 0; j < ntiles; ++j) {
        __syncthreads();
        // stage K (bf16 split) and V (single fp16)
        {
            int row = tid >> 2;
            int d0 = (tid & 3) * 16;
            const float* kg = k + base + (size_t)(j * 64 + row) * DM + d0;
            const float* vg = v + base + (size_t)(j * 64 + row) * DM + d0;
            #pragma unroll
            for (int c = 0; c < 2; ++c) {
                float4 f0 = *(const float4*)(kg + c * 8);
                float4 f1 = *(const float4*)(kg + c * 8 + 4);
                uint4 hh, ll;
                split_pack(f0.x, f0.y, hh.x, ll.x);
                split_pack(f0.z, f0.w, hh.y, ll.y);
                split_pack(f1.x, f1.y, hh.z, ll.z);
                split_pack(f1.z, f1.w, hh.w, ll.w);
                int chunk = (d0 >> 3) + c;
                int off = row * 128 + ((chunk ^ (row & 7)) << 4);
                *(uint4*)(Kh + off) = hh;
                *(uint4*)(Kl + off) = ll;
                float4 g0 = *(const float4*)(vg + c * 8);
                float4 g1 = *(const float4*)(vg + c * 8 + 4);
                uint4 vv;
                vv.x = packh2(g0.x, g0.y);
                vv.y = packh2(g0.z, g0.w);
                vv.z = packh2(g1.x, g1.y);
                vv.w = packh2(g1.z, g1.w);
                *(uint4*)(V16 + off) = vv;
            }
        }
        __syncthreads();

        float sacc[8][4];
        #pragma unroll
        for (int i = 0; i < 8; ++i)
            #pragma unroll
            for (int c = 0; c < 4; ++c) sacc[i][c] = 0.0f;

        #pragma unroll
        for (int nt = 0; nt < 8; nt += 2) {
            #pragma unroll
            for (int p = 0; p < 2; ++p) {
                int lr0 = 8 * nt + (lane & 7);
                int lc0 = (4 * p + (lane >> 3)) ^ (lr0 & 7);
                int lr1 = 8 * (nt + 1) + (lane & 7);
                int lc1 = (4 * p + (lane >> 3)) ^ (lr1 & 7);
                unsigned bkh0[4], bkl0[4], bkh1[4], bkl1[4];
                ldmx4(bkh0, uKh + lr0 * 128 + lc0 * 16);
                ldmx4(bkh1, uKh + lr1 * 128 + lc1 * 16);
                ldmx4(bkl0, uKl + lr0 * 128 + lc0 * 16);
                ldmx4(bkl1, uKl + lr1 * 128 + lc1 * 16);
                mma16(sacc[nt],     aqh[2 * p],     bkh0);
                mma16(sacc[nt + 1], aqh[2 * p],     bkh1);
                mma16(sacc[nt],     aql[2 * p],     bkh0);
                mma16(sacc[nt + 1], aql[2 * p],     bkh1);
                mma16(sacc[nt],     aqh[2 * p],     bkl0);
                mma16(sacc[nt + 1], aqh[2 * p],     bkl1);
                mma16(sacc[nt],     aqh[2 * p + 1], bkh0 + 2);
                mma16(sacc[nt + 1], aqh[2 * p + 1], bkh1 + 2);
                mma16(sacc[nt],     aql[2 * p + 1], bkh0 + 2);
                mma16(sacc[nt + 1], aql[2 * p + 1], bkh1 + 2);
                mma16(sacc[nt],     aqh[2 * p + 1], bkl0 + 2);
                mma16(sacc[nt + 1], aqh[2 * p + 1], bkl1 + 2);
            }
        }

        bool masked = (j >= nfull);
        int jb = j * 64;
        #pragma unroll
        for (int nt = 0; nt < 8; ++nt) {
            #pragma unroll
            for (int c = 0; c < 4; ++c) {
                float val = sacc[nt][c] * 0.125f;
                if (masked) {
                    int col = jb + 8 * nt + 2 * t + (c & 1);
                    int row = rowg0 + ((c >> 1) << 3);
                    if (col > row) val = -1e30f;
                }
                sacc[nt][c] = val;
            }
        }

        float m0 = -1e30f, m1 = -1e30f;
        #pragma unroll
        for (int nt = 0; nt < 8; ++nt) {
            m0 = fmaxf(m0, fmaxf(sacc[nt][0], sacc[nt][1]));
            m1 = fmaxf(m1, fmaxf(sacc[nt][2], sacc[nt][3]));
        }
        m0 = fmaxf(m0, __shfl_xor_sync(0xffffffffu, m0, 1));
        m0 = fmaxf(m0, __shfl_xor_sync(0xffffffffu, m0, 2));
        m1 = fmaxf(m1, __shfl_xor_sync(0xffffffffu, m1, 1));
        m1 = fmaxf(m1, __shfl_xor_sync(0xffffffffu, m1, 2));
        float mn0 = fmaxf(mrow0, m0);
        float mn1 = fmaxf(mrow1, m1);
        float corr0 = __expf(mrow0 - mn0);
        float corr1 = __expf(mrow1 - mn1);
        mrow0 = mn0; mrow1 = mn1;

        // P in single fp16
        unsigned ph01[8], ph23[8];
        float rs0 = 0.0f, rs1 = 0.0f;
        #pragma unroll
        for (int nt = 0; nt < 8; ++nt) {
            float p0 = __expf(sacc[nt][0] - mn0);
            float p1 = __expf(sacc[nt][1] - mn0);
            float p2 = __expf(sacc[nt][2] - mn1);
            float p3 = __expf(sacc[nt][3] - mn1);
            rs0 += p0 + p1;
            rs1 += p2 + p3;
            ph01[nt] = packh2(p0, p1);
            ph23[nt] = packh2(p2, p3);
        }
        rs0 += __shfl_xor_sync(0xffffffffu, rs0, 1);
        rs0 += __shfl_xor_sync(0xffffffffu, rs0, 2);
        rs1 += __shfl_xor_sync(0xffffffffu, rs1, 1);
        rs1 += __shfl_xor_sync(0xffffffffu, rs1, 2);
        lrow0 = lrow0 * corr0 + rs0;
        lrow1 = lrow1 * corr1 + rs1;
        #pragma unroll
        for (int nd = 0; nd < 8; ++nd) {
            oacc[nd][0] *= corr0; oacc[nd][1] *= corr0;
            oacc[nd][2] *= corr1; oacc[nd][3] *= corr1;
        }

        // O += P V, single fp16 both operands
        #pragma unroll
        for (int kc = 0; kc < 4; ++kc) {
            unsigned pa[4] = { ph01[2 * kc], ph23[2 * kc],
                               ph01[2 * kc + 1], ph23[2 * kc + 1] };
            #pragma unroll
            for (int nd2 = 0; nd2 < 4; ++nd2) {
                int lr = 16 * kc + (lane & 15);
                int lc = (2 * nd2 + (lane >> 4)) ^ (lr & 7);
                unsigned bv[4];
                ldmx4t(bv, uV + lr * 128 + lc * 16);
                mma16h(oacc[2 * nd2],     pa, bv);
                mma16h(oacc[2 * nd2 + 1], pa, bv + 2);
            }
        }
    }

    float inv0 = 1.0f / lrow0;
    float inv1 = 1.0f / lrow1;
    #pragma unroll
    for (int nd = 0; nd < 8; ++nd) {
        int col = 8 * nd + 2 * t;
        size_t off0 = base + (size_t)(rowg0) * DM + col;
        size_t off1 = base + (size_t)(rowg0 + 8) * DM + col;
        *(__half2*)(ao + off0) = __floats2half2_rn(oacc[nd][0] * inv0,
                                                   oacc[nd][1] * inv0);
        *(__half2*)(ao + off1) = __floats2half2_rn(oacc[nd][2] * inv1,
                                                   oacc[nd][3] * inv1);
    }
}

// ---------------------------------------------------------------------------
// Launch
// ---------------------------------------------------------------------------
extern "C" void kernel_launch(void* const* d_in, const int* in_sizes, int n_in,
                              void* d_out, int out_size) {
    const float* x     = (const float*)d_in[0];
    const float* wq    = (const float*)d_in[1];
    const float* wk    = (const float*)d_in[2];
    const float* wv    = (const float*)d_in[3];
    const float* wo    = (const float*)d_in[4];
    const float* ln1w  = (const float*)d_in[5];
    const float* ln2w  = (const float*)d_in[6];
    const float* upw   = (const float*)d_in[7];
    const float* gatew = (const float*)d_in[8];
    const float* downw = (const float*)d_in[9];
    float* out = (float*)d_out;

    float *q, *k, *v, *x1, *gate;
    cudaGetSymbolAddress((void**)&q,    g_q);
    cudaGetSymbolAddress((void**)&k,    g_k);
    cudaGetSymbolAddress((void**)&v,    g_v);
    cudaGetSymbolAddress((void**)&x1,   g_x1);
    cudaGetSymbolAddress((void**)&gate, g_gate);

    f16 *xn16, *ao16, *h16;
    f16 *wq16, *wk16, *wv16, *wo16, *up16, *gw16, *dw16;
    cudaGetSymbolAddress((void**)&xn16, g_xn16);
    cudaGetSymbolAddress((void**)&ao16, g_ao16);
    cudaGetSymbolAddress((void**)&h16,  g_h16);
    cudaGetSymbolAddress((void**)&wq16, g_wq16);
    cudaGetSymbolAddress((void**)&wk16, g_wk16);
    cudaGetSymbolAddress((void**)&wv16, g_wv16);
    cudaGetSymbolAddress((void**)&wo16, g_wo16);
    cudaGetSymbolAddress((void**)&up16, g_up16);
    cudaGetSymbolAddress((void**)&gw16, g_gw16);
    cudaGetSymbolAddress((void**)&dw16, g_dw16);

    cudaFuncSetAttribute(flash_kernel,
                         cudaFuncAttributeMaxDynamicSharedMemorySize, 57344);
    cudaFuncSetAttribute(hgemm_kernel<0>,
                         cudaFuncAttributeMaxDynamicSharedMemorySize, 32768);
    cudaFuncSetAttribute(hgemm_kernel<1>,
                         cudaFuncAttributeMaxDynamicSharedMemorySize, 32768);
    cudaFuncSetAttribute(hgemm_kernel<2>,
                         cudaFuncAttributeMaxDynamicSharedMemorySize, 32768);

    dim3 g1(DM / 128, M_ROWS / 128);    // (8, 64)
    dim3 g2(DFF / 128, M_ROWS / 128);   // (32, 64)

    // Weight conversions to fp16
    cvt16_kernel<<<DM * DM / 1024, 256>>>(wq, wq16);
    cvt16_kernel<<<DM * DM / 1024, 256>>>(wk, wk16);
    cvt16_kernel<<<DM * DM / 1024, 256>>>(wv, wv16);
    cvt16_kernel<<<DM * DM / 1024, 256>>>(wo, wo16);
    cvt16_kernel<<<DFF * DM / 1024, 256>>>(upw, up16);
    cvt16_kernel<<<DFF * DM / 1024, 256>>>(gatew, gw16);
    cvt16_kernel<<<DM * DFF / 1024, 256>>>(downw, dw16);

    // ln1 -> fp16 xn
    rmsnorm16_kernel<<<M_ROWS, 256>>>(x, ln1w, xn16);
    // q, k, v projections (1-term fp16)
    hgemm_kernel<0><<<g1, 256, 32768>>>(xn16, wq16, q, nullptr, nullptr, DM, DM);
    hgemm_kernel<0><<<g1, 256, 32768>>>(xn16, wk16, k, nullptr, nullptr, DM, DM);
    hgemm_kernel<0><<<g1, 256, 32768>>>(xn16, wv16, v, nullptr, nullptr, DM, DM);
    rope_kernel<<<(M_ROWS * 512) / 256, 256>>>(q, k);
    // tensor-core flash attention (fp16 ao output)
    flash_kernel<<<dim3(SEQ / 128, B_SZ * NHEAD), 256, 57344>>>(q, k, v, ao16);
    // o projection + residual
    hgemm_kernel<1><<<g1, 256, 32768>>>(ao16, wo16, x1, nullptr, x, DM, DM);
    // ln2 -> fp16 xn
    rmsnorm16_kernel<<<M_ROWS, 256>>>(x1, ln2w, xn16);
    // FFN
    hgemm_kernel<0><<<g2, 256, 32768>>>(xn16, gw16, gate, nullptr, nullptr, DFF, DM);
    hgemm_kernel<2><<<g2, 256, 32768>>>(xn16, up16, nullptr, h16, gate, DFF, DM);
    hgemm_kernel<1><<<g1, 256, 32768>>>(h16, dw16, out, nullptr, x1, DM, DFF);
}

// round 15
// speedup vs baseline: 2.0807x; 1.1413x over previous
#include <cuda_runtime.h>
#include <cuda_fp16.h>
#include <math.h>
#include <stdint.h>

// Problem constants
#define B_SZ 4
#define SEQ 2048
#define DM 1024
#define NHEAD 16
#define HD 64
#define DFF 4096
#define M_ROWS (B_SZ * SEQ)   // 8192

typedef __half f16;

// ---------------------------------------------------------------------------
// Scratch buffers
// ---------------------------------------------------------------------------
__device__ float g_x1[M_ROWS * DM];
__device__ float g_gate[M_ROWS * DFF];

__device__ f16 g_q16[M_ROWS * DM];
__device__ f16 g_k16[M_ROWS * DM];
__device__ f16 g_v16[M_ROWS * DM];
__device__ f16 g_xn16[M_ROWS * DM];
__device__ f16 g_ao16[M_ROWS * DM];
__device__ f16 g_h16[M_ROWS * DFF];

__device__ f16 g_wq16[DM * DM];
__device__ f16 g_wk16[DM * DM];
__device__ f16 g_wv16[DM * DM];
__device__ f16 g_wo16[DM * DM];
__device__ f16 g_up16[DFF * DM];
__device__ f16 g_gw16[DFF * DM];
__device__ f16 g_dw16[DM * DFF];

__device__ __forceinline__ unsigned packh2(float a, float b) {
    __half2 h = __floats2half2_rn(a, b);
    return *(unsigned*)&h;
}

// ---------------------------------------------------------------------------
// Elementwise kernels
// ---------------------------------------------------------------------------
__global__ __launch_bounds__(256)
void cvt16_kernel(const float* __restrict__ src, f16* __restrict__ dst) {
    size_t i = ((size_t)blockIdx.x * 256 + threadIdx.x) * 4;
    float4 v = *(const float4*)(src + i);
    *(__half2*)(dst + i)     = __floats2half2_rn(v.x, v.y);
    *(__half2*)(dst + i + 2) = __floats2half2_rn(v.z, v.w);
}

__global__ __launch_bounds__(256)
void rmsnorm16_kernel(const float* __restrict__ x,
                      const float* __restrict__ w,
                      f16* __restrict__ y) {
    int row = blockIdx.x;
    int tid = threadIdx.x;
    const float* xr = x + (size_t)row * DM;
    float4 v = *(const float4*)(xr + tid * 4);
    float s = v.x * v.x + v.y * v.y + v.z * v.z + v.w * v.w;
    #pragma unroll
    for (int off = 16; off; off >>= 1)
        s += __shfl_xor_sync(0xffffffffu, s, off);
    __shared__ float red[8];
    if ((tid & 31) == 0) red[tid >> 5] = s;
    __syncthreads();
    float tot = red[0] + red[1] + red[2] + red[3] +
                red[4] + red[5] + red[6] + red[7];
    float inv = rsqrtf(tot * (1.0f / DM) + 1e-5f);
    float4 wv = *(const float4*)(w + tid * 4);
    size_t o = (size_t)row * DM + tid * 4;
    *(__half2*)(y + o)     = __floats2half2_rn(v.x * inv * wv.x,
                                               v.y * inv * wv.y);
    *(__half2*)(y + o + 2) = __floats2half2_rn(v.z * inv * wv.z,
                                               v.w * inv * wv.w);
}

// RoPE on fp16 q/k, in place (rotation computed in fp32)
__global__ __launch_bounds__(256)
void rope16_kernel(f16* __restrict__ q, f16* __restrict__ k) {
    int idx = blockIdx.x * blockDim.x + threadIdx.x;
    if (idx >= M_ROWS * 512) return;
    int m  = idx >> 9;
    int pir = idx & 511;
    int h  = pir >> 5;
    int pp = pir & 31;
    int s  = m & (SEQ - 1);
    float inv_freq = expf(-(float)(2 * pp) * (9.210340371976184f / 64.0f));
    float ang = (float)s * inv_freq;
    float sn, cs;
    sincosf(ang, &sn, &cs);
    size_t off = (size_t)m * DM + h * HD + 2 * pp;
    __half2 qv = *(__half2*)(q + off);
    float qe = __low2float(qv), qo = __high2float(qv);
    *(__half2*)(q + off) = __floats2half2_rn(qe * cs - qo * sn,
                                             qo * cs + qe * sn);
    __half2 kv = *(__half2*)(k + off);
    float ke = __low2float(kv), ko = __high2float(kv);
    *(__half2*)(k + off) = __floats2half2_rn(ke * cs - ko * sn,
                                             ko * cs + ke * sn);
}

// ---------------------------------------------------------------------------
// mma / ldmatrix / cp.async primitives
// ---------------------------------------------------------------------------
__device__ __forceinline__ void mma16h(float* d, const unsigned* a,
                                       const unsigned* b) {
    asm volatile(
        "mma.sync.aligned.m16n8k16.row.col.f32.f16.f16.f32 "
        "{%0,%1,%2,%3}, {%4,%5,%6,%7}, {%8,%9}, {%0,%1,%2,%3};"
        : "+f"(d[0]), "+f"(d[1]), "+f"(d[2]), "+f"(d[3])
        : "r"(a[0]), "r"(a[1]), "r"(a[2]), "r"(a[3]), "r"(b[0]), "r"(b[1]));
}
__device__ __forceinline__ void ldmx4(unsigned* r, uint32_t addr) {
    asm volatile(
        "ldmatrix.sync.aligned.m8n8.x4.shared.b16 {%0,%1,%2,%3}, [%4];"
        : "=r"(r[0]), "=r"(r[1]), "=r"(r[2]), "=r"(r[3]) : "r"(addr));
}
__device__ __forceinline__ void ldmx4t(unsigned* r, uint32_t addr) {
    asm volatile(
        "ldmatrix.sync.aligned.m8n8.x4.trans.shared.b16 {%0,%1,%2,%3}, [%4];"
        : "=r"(r[0]), "=r"(r[1]), "=r"(r[2]), "=r"(r[3]) : "r"(addr));
}
__device__ __forceinline__ void cp_async16(uint32_t s, const void* g) {
    asm volatile("cp.async.cg.shared.global [%0], [%1], 16;\n"
                 :: "r"(s), "l"(g));
}
__device__ __forceinline__ void cp_commit() {
    asm volatile("cp.async.commit_group;\n");
}
__device__ __forceinline__ void cp_wait0() {
    asm volatile("cp.async.wait_group 0;\n");
}

// ---------------------------------------------------------------------------
// fp16 1-term GEMM: C[M,N] = A16[M,K] * W16[N,K]^T (+epilogue)
// EPI: 0 C=AB(fp32); 1 C=AB+aux(fp32); 2 C16=half(silu(AB)*aux); 3 C16=half(AB)
// ---------------------------------------------------------------------------
template <int EPI>
__global__ __launch_bounds__(256, 1)
void hgemm_kernel(const f16* __restrict__ A, const f16* __restrict__ W,
                  float* __restrict__ C, f16* __restrict__ C16,
                  const float* __restrict__ aux, int N, int K) {
    extern __shared__ char smc[];
    int tid = threadIdx.x;
    int wid = tid >> 5, lane = tid & 31;
    int g = lane >> 2, t = lane & 3;
    int wm = wid >> 2, wn = wid & 3;
    int m0 = blockIdx.y * 128;
    int n0 = blockIdx.x * 128;

    uint32_t smem_base = (uint32_t)__cvta_generic_to_shared(smc);

    int mm = lane >> 3;
    int aRowLoc = (mm & 1) * 8 + (lane & 7);
    int aCb = mm >> 1;
    int bRowLoc = (mm >> 1) * 8 + (lane & 7);
    int bCb = mm & 1;

    uint32_t aOff[4]; int aSw[4];
    #pragma unroll
    for (int mt = 0; mt < 4; ++mt) {
        int r = wm * 64 + mt * 16 + aRowLoc;
        aOff[mt] = r * 64;
        aSw[mt] = (r >> 1) & 3;
    }
    uint32_t bOff[2]; int bSw[2];
    #pragma unroll
    for (int nt2 = 0; nt2 < 2; ++nt2) {
        int r = wn * 32 + nt2 * 16 + bRowLoc;
        bOff[nt2] = r * 64;
        bSw[nt2] = (r >> 1) & 3;
    }

    float acc[4][4][4];
    #pragma unroll
    for (int i = 0; i < 4; ++i)
        #pragma unroll
        for (int j = 0; j < 4; ++j)
            #pragma unroll
            for (int c = 0; c < 4; ++c) acc[i][j][c] = 0.0f;

    int niter = K >> 5;
    int grow = tid >> 1;
    int gch0 = (tid & 1) << 1;

    #define STAGE(buf, k0)                                                      \
    {                                                                           \
        _Pragma("unroll")                                                       \
        for (int cc = 0; cc < 2; ++cc) {                                        \
            int ch = gch0 + cc;                                                 \
            uint32_t soff = (uint32_t)(grow * 64 +                              \
                ((ch ^ ((grow >> 1) & 3)) << 4));                               \
            size_t ga = (size_t)(m0 + grow) * K + (k0) + ch * 8;                \
            size_t gb = (size_t)(n0 + grow) * K + (k0) + ch * 8;                \
            uint32_t sb = smem_base + (buf) * 16384 + soff;                     \
            cp_async16(sb,        A + ga);                                      \
            cp_async16(sb + 8192, W + gb);                                      \
        }                                                                       \
        cp_commit();                                                            \
    }

    STAGE(0, 0);
    cp_wait0();
    __syncthreads();

    int buf = 0;
    for (int it = 0; it < niter; ++it) {
        if (it + 1 < niter) STAGE(buf ^ 1, (it + 1) << 5);

        uint32_t tA = smem_base + buf * 16384;
        uint32_t tB = tA + 8192;

        #pragma unroll
        for (int ck = 0; ck < 2; ++ck) {
            unsigned bf[2][4];
            #pragma unroll
            for (int nt2 = 0; nt2 < 2; ++nt2) {
                uint32_t off = bOff[nt2] +
                               (((2 * ck + bCb) ^ bSw[nt2]) << 4);
                ldmx4(bf[nt2], tB + off);
            }
            #pragma unroll
            for (int mp = 0; mp < 2; ++mp) {
                int mt0 = 2 * mp, mt1 = 2 * mp + 1;
                uint32_t off0 = aOff[mt0] + (((2 * ck + aCb) ^ aSw[mt0]) << 4);
                uint32_t off1 = aOff[mt1] + (((2 * ck + aCb) ^ aSw[mt1]) << 4);
                unsigned a0[4], a1[4];
                ldmx4(a0, tA + off0);
                ldmx4(a1, tA + off1);
                mma16h(acc[mt0][0], a0, bf[0]);
                mma16h(acc[mt0][1], a0, bf[0] + 2);
                mma16h(acc[mt0][2], a0, bf[1]);
                mma16h(acc[mt0][3], a0, bf[1] + 2);
                mma16h(acc[mt1][0], a1, bf[0]);
                mma16h(acc[mt1][1], a1, bf[0] + 2);
                mma16h(acc[mt1][2], a1, bf[1]);
                mma16h(acc[mt1][3], a1, bf[1] + 2);
            }
        }

        if (it + 1 < niter) cp_wait0();
        __syncthreads();
        buf ^= 1;
    }
    #undef STAGE

    #pragma unroll
    for (int mt = 0; mt < 4; ++mt) {
        #pragma unroll
        for (int nt = 0; nt < 4; ++nt) {
            int rb = m0 + wm * 64 + mt * 16 + g;
            int cb = n0 + wn * 32 + nt * 8 + 2 * t;
            #pragma unroll
            for (int half = 0; half < 2; ++half) {
                size_t off = (size_t)(rb + half * 8) * N + cb;
                float u0 = acc[mt][nt][half * 2];
                float u1 = acc[mt][nt][half * 2 + 1];
                if (EPI == 0) {
                    C[off] = u0; C[off + 1] = u1;
                } else if (EPI == 1) {
                    C[off] = u0 + aux[off];
                    C[off + 1] = u1 + aux[off + 1];
                } else if (EPI == 2) {
                    float s0 = 1.0f / (1.0f + __expf(-u0));
                    float s1 = 1.0f / (1.0f + __expf(-u1));
                    *(__half2*)(C16 + off) =
                        __floats2half2_rn(u0 * s0 * aux[off],
                                          u1 * s1 * aux[off + 1]);
                } else {
                    *(__half2*)(C16 + off) = __floats2half2_rn(u0, u1);
                }
            }
        }
    }
}

// ---------------------------------------------------------------------------
// fp16 flash attention (causal). All operands single fp16.
// Block = 128 q rows of one (b,h); K tiles of 64, double-buffered cp.async.
// smem: Q 16K | K[2] 8K each | V[2] 8K each = 48KB.
// ---------------------------------------------------------------------------
__global__ __launch_bounds__(256, 1)
void flash_kernel(const f16* __restrict__ q, const f16* __restrict__ k,
                  const f16* __restrict__ v, f16* __restrict__ ao) {
    extern __shared__ char sm[];
    uint32_t uQ = (uint32_t)__cvta_generic_to_shared(sm);
    uint32_t uK = uQ + 16384;   // + buf*8192
    uint32_t uV = uQ + 32768;   // + buf*8192

    int tid = threadIdx.x;
    int wid = tid >> 5, lane = tid & 31;
    int g = lane >> 2, t = lane & 3;
    int qb = blockIdx.x;
    int bh = blockIdx.y;
    int b = bh >> 4, h = bh & 15;
    int i0 = qb * 128;
    size_t base = ((size_t)b * SEQ) * DM + h * HD;

    int ntiles = 2 * qb + 2;
    int nfull  = 2 * qb;

    // stage K,V tile j into buffer buf
    #define STAGEKV(j, bufv)                                                   \
    {                                                                          \
        int row = tid >> 2;                                                    \
        int ch0 = (tid & 3) * 2;                                               \
        const f16* kg = k + base + (size_t)((j) * 64 + row) * DM + ch0 * 8;    \
        const f16* vg = v + base + (size_t)((j) * 64 + row) * DM + ch0 * 8;    \
        _Pragma("unroll")                                                      \
        for (int cc = 0; cc < 2; ++cc) {                                       \
            int ch = ch0 + cc;                                                 \
            uint32_t so = (uint32_t)(row * 128 + ((ch ^ (row & 7)) << 4));     \
            cp_async16(uK + (bufv) * 8192 + so, kg + cc * 8);                  \
            cp_async16(uV + (bufv) * 8192 + so, vg + cc * 8);                  \
        }                                                                      \
        cp_commit();                                                           \
    }

    // stage Q (128 rows) + first K/V tile
    {
        int row = tid >> 1;
        int ch0 = (tid & 1) * 4;
        const f16* qg = q + base + (size_t)(i0 + row) * DM + ch0 * 8;
        #pragma unroll
        for (int cc = 0; cc < 4; ++cc) {
            int ch = ch0 + cc;
            uint32_t so = (uint32_t)(row * 128 + ((ch ^ (row & 7)) << 4));
            cp_async16(uQ + so, qg + cc * 8);
        }
        cp_commit();
    }
    STAGEKV(0, 0);
    cp_wait0();
    __syncthreads();

    // hoist Q fragments: rows 16*wid..+15, 4 k16 chunks
    int r0 = 16 * wid;
    unsigned aq[4][4];
    #pragma unroll
    for (int kc = 0; kc < 4; ++kc) {
        int m = lane >> 3;
        int lr = r0 + (lane & 7) + (m & 1) * 8;
        int lc = (2 * kc + (m >> 1)) ^ (lr & 7);
        ldmx4(aq[kc], uQ + lr * 128 + lc * 16);
    }

    float oacc[8][4];
    #pragma unroll
    for (int i = 0; i < 8; ++i)
        #pragma unroll
        for (int c = 0; c < 4; ++c) oacc[i][c] = 0.0f;
    float mrow0 = -1e30f, mrow1 = -1e30f;
    float lrow0 = 0.0f, lrow1 = 0.0f;
    int rowg0 = i0 + r0 + g;

    for (int j = 0; j < ntiles; ++j) {
        int buf = j & 1;
        if (j + 1 < ntiles) STAGEKV(j + 1, buf ^ 1);
        uint32_t uKb = uK + buf * 8192;
        uint32_t uVb = uV + buf * 8192;

        // S = Q K^T  (1-term fp16: 16 ldmx4 + 32 mmas)
        float sacc[8][4];
        #pragma unroll
        for (int i = 0; i < 8; ++i)
            #pragma unroll
            for (int c = 0; c < 4; ++c) sacc[i][c] = 0.0f;

        #pragma unroll
        for (int nt = 0; nt < 8; ++nt) {
            #pragma unroll
            for (int p = 0; p < 2; ++p) {
                int lr = 8 * nt + (lane & 7);
                int lc = (4 * p + (lane >> 3)) ^ (lr & 7);
                unsigned bk[4];
                ldmx4(bk, uKb + lr * 128 + lc * 16);
                mma16h(sacc[nt], aq[2 * p],     bk);
                mma16h(sacc[nt], aq[2 * p + 1], bk + 2);
            }
        }

        bool masked = (j >= nfull);
        int jb = j * 64;
        #pragma unroll
        for (int nt = 0; nt < 8; ++nt) {
            #pragma unroll
            for (int c = 0; c < 4; ++c) {
                float val = sacc[nt][c] * 0.125f;
                if (masked) {
                    int col = jb + 8 * nt + 2 * t + (c & 1);
                    int row = rowg0 + ((c >> 1) << 3);
                    if (col > row) val = -1e30f;
                }
                sacc[nt][c] = val;
            }
        }

        float m0 = -1e30f, m1 = -1e30f;
        #pragma unroll
        for (int nt = 0; nt < 8; ++nt) {
            m0 = fmaxf(m0, fmaxf(sacc[nt][0], sacc[nt][1]));
            m1 = fmaxf(m1, fmaxf(sacc[nt][2], sacc[nt][3]));
        }
        m0 = fmaxf(m0, __shfl_xor_sync(0xffffffffu, m0, 1));
        m0 = fmaxf(m0, __shfl_xor_sync(0xffffffffu, m0, 2));
        m1 = fmaxf(m1, __shfl_xor_sync(0xffffffffu, m1, 1));
        m1 = fmaxf(m1, __shfl_xor_sync(0xffffffffu, m1, 2));
        float mn0 = fmaxf(mrow0, m0);
        float mn1 = fmaxf(mrow1, m1);
        float corr0 = __expf(mrow0 - mn0);
        float corr1 = __expf(mrow1 - mn1);
        mrow0 = mn0; mrow1 = mn1;

        unsigned ph01[8], ph23[8];
        float rs0 = 0.0f, rs1 = 0.0f;
        #pragma unroll
        for (int nt = 0; nt < 8; ++nt) {
            float p0 = __expf(sacc[nt][0] - mn0);
            float p1 = __expf(sacc[nt][1] - mn0);
            float p2 = __expf(sacc[nt][2] - mn1);
            float p3 = __expf(sacc[nt][3] - mn1);
            rs0 += p0 + p1;
            rs1 += p2 + p3;
            ph01[nt] = packh2(p0, p1);
            ph23[nt] = packh2(p2, p3);
        }
        rs0 += __shfl_xor_sync(0xffffffffu, rs0, 1);
        rs0 += __shfl_xor_sync(0xffffffffu, rs0, 2);
        rs1 += __shfl_xor_sync(0xffffffffu, rs1, 1);
        rs1 += __shfl_xor_sync(0xffffffffu, rs1, 2);
        lrow0 = lrow0 * corr0 + rs0;
        lrow1 = lrow1 * corr1 + rs1;
        #pragma unroll
        for (int nd = 0; nd < 8; ++nd) {
            oacc[nd][0] *= corr0; oacc[nd][1] *= corr0;
            oacc[nd][2] *= corr1; oacc[nd][3] *= corr1;
        }

        // O += P V  (1-term fp16: 16 ldmx4t + 32 mmas)
        #pragma unroll
        for (int kc = 0; kc < 4; ++kc) {
            unsigned pa[4] = { ph01[2 * kc], ph23[2 * kc],
                               ph01[2 * kc + 1], ph23[2 * kc + 1] };
            #pragma unroll
            for (int nd2 = 0; nd2 < 4; ++nd2) {
                int lr = 16 * kc + (lane & 15);
                int lc = (2 * nd2 + (lane >> 4)) ^ (lr & 7);
                unsigned bv[4];
                ldmx4t(bv, uVb + lr * 128 + lc * 16);
                mma16h(oacc[2 * nd2],     pa, bv);
                mma16h(oacc[2 * nd2 + 1], pa, bv + 2);
            }
        }

        // wait for prefetched next tile; barrier protects buffer reuse
        if (j + 1 < ntiles) cp_wait0();
        __syncthreads();
    }
    #undef STAGEKV

    float inv0 = 1.0f / lrow0;
    float inv1 = 1.0f / lrow1;
    #pragma unroll
    for (int nd = 0; nd < 8; ++nd) {
        int col = 8 * nd + 2 * t;
        size_t off0 = base + (size_t)(rowg0) * DM + col;
        size_t off1 = base + (size_t)(rowg0 + 8) * DM + col;
        *(__half2*)(ao + off0) = __floats2half2_rn(oacc[nd][0] * inv0,
                                                   oacc[nd][1] * inv0);
        *(__half2*)(ao + off1) = __floats2half2_rn(oacc[nd][2] * inv1,
                                                   oacc[nd][3] * inv1);
    }
}

// ---------------------------------------------------------------------------
// Launch
// ---------------------------------------------------------------------------
extern "C" void kernel_launch(void* const* d_in, const int* in_sizes, int n_in,
                              void* d_out, int out_size) {
    const float* x     = (const float*)d_in[0];
    const float* wq    = (const float*)d_in[1];
    const float* wk    = (const float*)d_in[2];
    const float* wv    = (const float*)d_in[3];
    const float* wo    = (const float*)d_in[4];
    const float* ln1w  = (const float*)d_in[5];
    const float* ln2w  = (const float*)d_in[6];
    const float* upw   = (const float*)d_in[7];
    const float* gatew = (const float*)d_in[8];
    const float* downw = (const float*)d_in[9];
    float* out = (float*)d_out;

    float *x1, *gate;
    cudaGetSymbolAddress((void**)&x1,   g_x1);
    cudaGetSymbolAddress((void**)&gate, g_gate);

    f16 *q16, *k16, *v16, *xn16, *ao16, *h16;
    f16 *wq16, *wk16, *wv16, *wo16, *up16, *gw16, *dw16;
    cudaGetSymbolAddress((void**)&q16,  g_q16);
    cudaGetSymbolAddress((void**)&k16,  g_k16);
    cudaGetSymbolAddress((void**)&v16,  g_v16);
    cudaGetSymbolAddress((void**)&xn16, g_xn16);
    cudaGetSymbolAddress((void**)&ao16, g_ao16);
    cudaGetSymbolAddress((void**)&h16,  g_h16);
    cudaGetSymbolAddress((void**)&wq16, g_wq16);
    cudaGetSymbolAddress((void**)&wk16, g_wk16);
    cudaGetSymbolAddress((void**)&wv16, g_wv16);
    cudaGetSymbolAddress((void**)&wo16, g_wo16);
    cudaGetSymbolAddress((void**)&up16, g_up16);
    cudaGetSymbolAddress((void**)&gw16, g_gw16);
    cudaGetSymbolAddress((void**)&dw16, g_dw16);

    cudaFuncSetAttribute(flash_kernel,
                         cudaFuncAttributeMaxDynamicSharedMemorySize, 49152);
    cudaFuncSetAttribute(hgemm_kernel<0>,
                         cudaFuncAttributeMaxDynamicSharedMemorySize, 32768);
    cudaFuncSetAttribute(hgemm_kernel<1>,
                         cudaFuncAttributeMaxDynamicSharedMemorySize, 32768);
    cudaFuncSetAttribute(hgemm_kernel<2>,
                         cudaFuncAttributeMaxDynamicSharedMemorySize, 32768);
    cudaFuncSetAttribute(hgemm_kernel<3>,
                         cudaFuncAttributeMaxDynamicSharedMemorySize, 32768);

    dim3 g1(DM / 128, M_ROWS / 128);    // (8, 64)
    dim3 g2(DFF / 128, M_ROWS / 128);   // (32, 64)

    // Weight conversions to fp16
    cvt16_kernel<<<DM * DM / 1024, 256>>>(wq, wq16);
    cvt16_kernel<<<DM * DM / 1024, 256>>>(wk, wk16);
    cvt16_kernel<<<DM * DM / 1024, 256>>>(wv, wv16);
    cvt16_kernel<<<DM * DM / 1024, 256>>>(wo, wo16);
    cvt16_kernel<<<DFF * DM / 1024, 256>>>(upw, up16);
    cvt16_kernel<<<DFF * DM / 1024, 256>>>(gatew, gw16);
    cvt16_kernel<<<DM * DFF / 1024, 256>>>(downw, dw16);

    // ln1 -> fp16 xn
    rmsnorm16_kernel<<<M_ROWS, 256>>>(x, ln1w, xn16);
    // q, k, v projections -> fp16 outputs
    hgemm_kernel<3><<<g1, 256, 32768>>>(xn16, wq16, nullptr, q16, nullptr, DM, DM);
    hgemm_kernel<3><<<g1, 256, 32768>>>(xn16, wk16, nullptr, k16, nullptr, DM, DM);
    hgemm_kernel<3><<<g1, 256, 32768>>>(xn16, wv16, nullptr, v16, nullptr, DM, DM);
    rope16_kernel<<<(M_ROWS * 512) / 256, 256>>>(q16, k16);
    // fp16 flash attention
    flash_kernel<<<dim3(SEQ / 128, B_SZ * NHEAD), 256, 49152>>>(q16, k16, v16, ao16);
    // o projection + residual
    hgemm_kernel<1><<<g1, 256, 32768>>>(ao16, wo16, x1, nullptr, x, DM, DM);
    // ln2 -> fp16 xn
    rmsnorm16_kernel<<<M_ROWS, 256>>>(x1, ln2w, xn16);
    // FFN
    hgemm_kernel<0><<<g2, 256, 32768>>>(xn16, gw16, gate, nullptr, nullptr, DFF, DM);
    hgemm_kernel<2><<<g2, 256, 32768>>>(xn16, up16, nullptr, h16, gate, DFF, DM);
    hgemm_kernel<1><<<g1, 256, 32768>>>(h16, dw16, out, nullptr, x1, DM, DFF);
}

// round 16
// speedup vs baseline: 2.8870x; 1.3875x over previous
#include <cuda_runtime.h>
#include <cuda_fp16.h>
#include <math.h>
#include <stdint.h>

// Problem constants
#define B_SZ 4
#define SEQ 2048
#define DM 1024
#define NHEAD 16
#define HD 64
#define DFF 4096
#define M_ROWS (B_SZ * SEQ)   // 8192
#define QLD 3072              // fused qkv row stride

typedef __half f16;

// ---------------------------------------------------------------------------
// Scratch buffers
// ---------------------------------------------------------------------------
__device__ float g_x1[M_ROWS * DM];
__device__ float g_gate[M_ROWS * DFF];

__device__ f16 g_qkv16[M_ROWS * QLD];
__device__ f16 g_xn16[M_ROWS * DM];
__device__ f16 g_ao16[M_ROWS * DM];
__device__ f16 g_h16[M_ROWS * DFF];

__device__ f16 g_wqkv16[3 * DM * DM];
__device__ f16 g_wo16[DM * DM];
__device__ f16 g_up16[DFF * DM];
__device__ f16 g_gw16[DFF * DM];
__device__ f16 g_dw16[DM * DFF];

__device__ __forceinline__ unsigned packh2(float a, float b) {
    __half2 h = __floats2half2_rn(a, b);
    return *(unsigned*)&h;
}

// ---------------------------------------------------------------------------
// Elementwise kernels
// ---------------------------------------------------------------------------
__global__ __launch_bounds__(256)
void cvt16_kernel(const float* __restrict__ src, f16* __restrict__ dst) {
    size_t i = ((size_t)blockIdx.x * 256 + threadIdx.x) * 4;
    float4 v = *(const float4*)(src + i);
    *(__half2*)(dst + i)     = __floats2half2_rn(v.x, v.y);
    *(__half2*)(dst + i + 2) = __floats2half2_rn(v.z, v.w);
}

__global__ __launch_bounds__(256)
void rmsnorm16_kernel(const float* __restrict__ x,
                      const float* __restrict__ w,
                      f16* __restrict__ y) {
    int row = blockIdx.x;
    int tid = threadIdx.x;
    const float* xr = x + (size_t)row * DM;
    float4 v = *(const float4*)(xr + tid * 4);
    float s = v.x * v.x + v.y * v.y + v.z * v.z + v.w * v.w;
    #pragma unroll
    for (int off = 16; off; off >>= 1)
        s += __shfl_xor_sync(0xffffffffu, s, off);
    __shared__ float red[8];
    if ((tid & 31) == 0) red[tid >> 5] = s;
    __syncthreads();
    float tot = red[0] + red[1] + red[2] + red[3] +
                red[4] + red[5] + red[6] + red[7];
    float inv = rsqrtf(tot * (1.0f / DM) + 1e-5f);
    float4 wv = *(const float4*)(w + tid * 4);
    size_t o = (size_t)row * DM + tid * 4;
    *(__half2*)(y + o)     = __floats2half2_rn(v.x * inv * wv.x,
                                               v.y * inv * wv.y);
    *(__half2*)(y + o + 2) = __floats2half2_rn(v.z * inv * wv.z,
                                               v.w * inv * wv.w);
}

// RoPE on fused qkv buffer (q at +0, k at +1024), in place
__global__ __launch_bounds__(256)
void rope16_kernel(f16* __restrict__ qkv) {
    int idx = blockIdx.x * blockDim.x + threadIdx.x;
    if (idx >= M_ROWS * 512) return;
    int m  = idx >> 9;
    int pir = idx & 511;
    int h  = pir >> 5;
    int pp = pir & 31;
    int s  = m & (SEQ - 1);
    float inv_freq = expf(-(float)(2 * pp) * (9.210340371976184f / 64.0f));
    float ang = (float)s * inv_freq;
    float sn, cs;
    sincosf(ang, &sn, &cs);
    size_t off = (size_t)m * QLD + h * HD + 2 * pp;
    __half2 qv = *(__half2*)(qkv + off);
    float qe = __low2float(qv), qo = __high2float(qv);
    *(__half2*)(qkv + off) = __floats2half2_rn(qe * cs - qo * sn,
                                               qo * cs + qe * sn);
    __half2 kv = *(__half2*)(qkv + off + 1024);
    float ke = __low2float(kv), ko = __high2float(kv);
    *(__half2*)(qkv + off + 1024) = __floats2half2_rn(ke * cs - ko * sn,
                                                      ko * cs + ke * sn);
}

// ---------------------------------------------------------------------------
// mma / ldmatrix / cp.async primitives
// ---------------------------------------------------------------------------
__device__ __forceinline__ void mma16h(float* d, const unsigned* a,
                                       const unsigned* b) {
    asm volatile(
        "mma.sync.aligned.m16n8k16.row.col.f32.f16.f16.f32 "
        "{%0,%1,%2,%3}, {%4,%5,%6,%7}, {%8,%9}, {%0,%1,%2,%3};"
        : "+f"(d[0]), "+f"(d[1]), "+f"(d[2]), "+f"(d[3])
        : "r"(a[0]), "r"(a[1]), "r"(a[2]), "r"(a[3]), "r"(b[0]), "r"(b[1]));
}
__device__ __forceinline__ void ldmx4(unsigned* r, uint32_t addr) {
    asm volatile(
        "ldmatrix.sync.aligned.m8n8.x4.shared.b16 {%0,%1,%2,%3}, [%4];"
        : "=r"(r[0]), "=r"(r[1]), "=r"(r[2]), "=r"(r[3]) : "r"(addr));
}
__device__ __forceinline__ void ldmx4t(unsigned* r, uint32_t addr) {
    asm volatile(
        "ldmatrix.sync.aligned.m8n8.x4.trans.shared.b16 {%0,%1,%2,%3}, [%4];"
        : "=r"(r[0]), "=r"(r[1]), "=r"(r[2]), "=r"(r[3]) : "r"(addr));
}
__device__ __forceinline__ void cp_async16(uint32_t s, const void* g) {
    asm volatile("cp.async.cg.shared.global [%0], [%1], 16;\n"
                 :: "r"(s), "l"(g));
}
__device__ __forceinline__ void cp_commit() {
    asm volatile("cp.async.commit_group;\n");
}
__device__ __forceinline__ void cp_wait0() {
    asm volatile("cp.async.wait_group 0;\n");
}
__device__ __forceinline__ void cp_wait1() {
    asm volatile("cp.async.wait_group 1;\n");
}

// ---------------------------------------------------------------------------
// fp16 1-term GEMM, 3-stage cp.async pipeline, 2 CTAs/SM target.
// C[M,N] = A16[M,K] * W16[N,K]^T (+epilogue)
// EPI: 0 C=AB(fp32); 1 C=AB+aux(fp32); 2 C16=half(silu(AB)*aux); 3 C16=half(AB)
// smem: 3 stages x (A 8KB | W 8KB) = 48KB.
// ---------------------------------------------------------------------------
template <int EPI>
__global__ __launch_bounds__(256, 2)
void hgemm_kernel(const f16* __restrict__ A, const f16* __restrict__ W,
                  float* __restrict__ C, f16* __restrict__ C16,
                  const float* __restrict__ aux, int N, int K) {
    extern __shared__ char smc[];
    int tid = threadIdx.x;
    int wid = tid >> 5, lane = tid & 31;
    int g = lane >> 2, t = lane & 3;
    int wm = wid >> 2, wn = wid & 3;
    int m0 = blockIdx.y * 128;
    int n0 = blockIdx.x * 128;

    uint32_t smem_base = (uint32_t)__cvta_generic_to_shared(smc);

    int mm = lane >> 3;
    int aRowLoc = (mm & 1) * 8 + (lane & 7);
    int aCb = mm >> 1;
    int bRowLoc = (mm >> 1) * 8 + (lane & 7);
    int bCb = mm & 1;

    uint32_t aOff[4]; int aSw[4];
    #pragma unroll
    for (int mt = 0; mt < 4; ++mt) {
        int r = wm * 64 + mt * 16 + aRowLoc;
        aOff[mt] = r * 64;
        aSw[mt] = (r >> 1) & 3;
    }
    uint32_t bOff[2]; int bSw[2];
    #pragma unroll
    for (int nt2 = 0; nt2 < 2; ++nt2) {
        int r = wn * 32 + nt2 * 16 + bRowLoc;
        bOff[nt2] = r * 64;
        bSw[nt2] = (r >> 1) & 3;
    }

    float acc[4][4][4];
    #pragma unroll
    for (int i = 0; i < 4; ++i)
        #pragma unroll
        for (int j = 0; j < 4; ++j)
            #pragma unroll
            for (int c = 0; c < 4; ++c) acc[i][j][c] = 0.0f;

    int niter = K >> 5;
    int grow = tid >> 1;
    int gch0 = (tid & 1) << 1;

    #define STAGE(buf, k0)                                                      \
    {                                                                           \
        _Pragma("unroll")                                                       \
        for (int cc = 0; cc < 2; ++cc) {                                        \
            int ch = gch0 + cc;                                                 \
            uint32_t soff = (uint32_t)(grow * 64 +                              \
                ((ch ^ ((grow >> 1) & 3)) << 4));                               \
            size_t ga = (size_t)(m0 + grow) * K + (k0) + ch * 8;                \
            size_t gb = (size_t)(n0 + grow) * K + (k0) + ch * 8;                \
            uint32_t sb = smem_base + (buf) * 16384 + soff;                     \
            cp_async16(sb,        A + ga);                                      \
            cp_async16(sb + 8192, W + gb);                                      \
        }                                                                       \
        cp_commit();                                                            \
    }

    // prologue: stages 0 and 1 (niter >= 2 always here)
    STAGE(0, 0);
    STAGE(1, 32);

    int buf = 0;
    for (int it = 0; it < niter; ++it) {
        if (it == niter - 1) cp_wait0(); else cp_wait1();
        __syncthreads();
        if (it + 2 < niter) {
            int nb = buf + 2; if (nb >= 3) nb -= 3;
            STAGE(nb, (it + 2) << 5);
        }

        uint32_t tA = smem_base + buf * 16384;
        uint32_t tB = tA + 8192;

        #pragma unroll
        for (int ck = 0; ck < 2; ++ck) {
            unsigned bf[2][4];
            #pragma unroll
            for (int nt2 = 0; nt2 < 2; ++nt2) {
                uint32_t off = bOff[nt2] +
                               (((2 * ck + bCb) ^ bSw[nt2]) << 4);
                ldmx4(bf[nt2], tB + off);
            }
            #pragma unroll
            for (int mp = 0; mp < 2; ++mp) {
                int mt0 = 2 * mp, mt1 = 2 * mp + 1;
                uint32_t off0 = aOff[mt0] + (((2 * ck + aCb) ^ aSw[mt0]) << 4);
                uint32_t off1 = aOff[mt1] + (((2 * ck + aCb) ^ aSw[mt1]) << 4);
                unsigned a0[4], a1[4];
                ldmx4(a0, tA + off0);
                ldmx4(a1, tA + off1);
                mma16h(acc[mt0][0], a0, bf[0]);
                mma16h(acc[mt0][1], a0, bf[0] + 2);
                mma16h(acc[mt0][2], a0, bf[1]);
                mma16h(acc[mt0][3], a0, bf[1] + 2);
                mma16h(acc[mt1][0], a1, bf[0]);
                mma16h(acc[mt1][1], a1, bf[0] + 2);
                mma16h(acc[mt1][2], a1, bf[1]);
                mma16h(acc[mt1][3], a1, bf[1] + 2);
            }
        }

        if (++buf == 3) buf = 0;
    }
    #undef STAGE

    #pragma unroll
    for (int mt = 0; mt < 4; ++mt) {
        #pragma unroll
        for (int nt = 0; nt < 4; ++nt) {
            int rb = m0 + wm * 64 + mt * 16 + g;
            int cb = n0 + wn * 32 + nt * 8 + 2 * t;
            #pragma unroll
            for (int half = 0; half < 2; ++half) {
                size_t off = (size_t)(rb + half * 8) * N + cb;
                float u0 = acc[mt][nt][half * 2];
                float u1 = acc[mt][nt][half * 2 + 1];
                if (EPI == 0) {
                    C[off] = u0; C[off + 1] = u1;
                } else if (EPI == 1) {
                    C[off] = u0 + aux[off];
                    C[off + 1] = u1 + aux[off + 1];
                } else if (EPI == 2) {
                    float s0 = 1.0f / (1.0f + __expf(-u0));
                    float s1 = 1.0f / (1.0f + __expf(-u1));
                    *(__half2*)(C16 + off) =
                        __floats2half2_rn(u0 * s0 * aux[off],
                                          u1 * s1 * aux[off + 1]);
                } else {
                    *(__half2*)(C16 + off) = __floats2half2_rn(u0, u1);
                }
            }
        }
    }
}

// ---------------------------------------------------------------------------
// fp16 flash attention (causal) over fused qkv buffer (stride QLD).
// smem: Q 16K | K[2] 8K each | V[2] 8K each = 48KB.
// ---------------------------------------------------------------------------
__global__ __launch_bounds__(256, 1)
void flash_kernel(const f16* __restrict__ qkv, f16* __restrict__ ao) {
    extern __shared__ char sm[];
    uint32_t uQ = (uint32_t)__cvta_generic_to_shared(sm);
    uint32_t uK = uQ + 16384;
    uint32_t uV = uQ + 32768;

    int tid = threadIdx.x;
    int wid = tid >> 5, lane = tid & 31;
    int g = lane >> 2, t = lane & 3;
    int qb = blockIdx.x;
    int bh = blockIdx.y;
    int b = bh >> 4, h = bh & 15;
    int i0 = qb * 128;
    size_t base  = ((size_t)b * SEQ) * QLD + h * HD;   // q; k=+1024, v=+2048
    size_t obase = ((size_t)b * SEQ) * DM + h * HD;

    int ntiles = 2 * qb + 2;
    int nfull  = 2 * qb;

    #define STAGEKV(j, bufv)                                                   \
    {                                                                          \
        int row = tid >> 2;                                                    \
        int ch0 = (tid & 3) * 2;                                               \
        const f16* kg = qkv + base + 1024 +                                    \
                        (size_t)((j) * 64 + row) * QLD + ch0 * 8;              \
        const f16* vg = qkv + base + 2048 +                                    \
                        (size_t)((j) * 64 + row) * QLD + ch0 * 8;              \
        _Pragma("unroll")                                                      \
        for (int cc = 0; cc < 2; ++cc) {                                       \
            int ch = ch0 + cc;                                                 \
            uint32_t so = (uint32_t)(row * 128 + ((ch ^ (row & 7)) << 4));     \
            cp_async16(uK + (bufv) * 8192 + so, kg + cc * 8);                  \
            cp_async16(uV + (bufv) * 8192 + so, vg + cc * 8);                  \
        }                                                                      \
        cp_commit();                                                           \
    }

    {
        int row = tid >> 1;
        int ch0 = (tid & 1) * 4;
        const f16* qg = qkv + base + (size_t)(i0 + row) * QLD + ch0 * 8;
        #pragma unroll
        for (int cc = 0; cc < 4; ++cc) {
            int ch = ch0 + cc;
            uint32_t so = (uint32_t)(row * 128 + ((ch ^ (row & 7)) << 4));
            cp_async16(uQ + so, qg + cc * 8);
        }
        cp_commit();
    }
    STAGEKV(0, 0);
    cp_wait0();
    __syncthreads();

    int r0 = 16 * wid;
    unsigned aq[4][4];
    #pragma unroll
    for (int kc = 0; kc < 4; ++kc) {
        int m = lane >> 3;
        int lr = r0 + (lane & 7) + (m & 1) * 8;
        int lc = (2 * kc + (m >> 1)) ^ (lr & 7);
        ldmx4(aq[kc], uQ + lr * 128 + lc * 16);
    }

    float oacc[8][4];
    #pragma unroll
    for (int i = 0; i < 8; ++i)
        #pragma unroll
        for (int c = 0; c < 4; ++c) oacc[i][c] = 0.0f;
    float mrow0 = -1e30f, mrow1 = -1e30f;
    float lrow0 = 0.0f, lrow1 = 0.0f;
    int rowg0 = i0 + r0 + g;

    for (int j = 0; j < ntiles; ++j) {
        int buf = j & 1;
        if (j + 1 < ntiles) STAGEKV(j + 1, buf ^ 1);
        uint32_t uKb = uK + buf * 8192;
        uint32_t uVb = uV + buf * 8192;

        float sacc[8][4];
        #pragma unroll
        for (int i = 0; i < 8; ++i)
            #pragma unroll
            for (int c = 0; c < 4; ++c) sacc[i][c] = 0.0f;

        #pragma unroll
        for (int nt = 0; nt < 8; ++nt) {
            #pragma unroll
            for (int p = 0; p < 2; ++p) {
                int lr = 8 * nt + (lane & 7);
                int lc = (4 * p + (lane >> 3)) ^ (lr & 7);
                unsigned bk[4];
                ldmx4(bk, uKb + lr * 128 + lc * 16);
                mma16h(sacc[nt], aq[2 * p],     bk);
                mma16h(sacc[nt], aq[2 * p + 1], bk + 2);
            }
        }

        bool masked = (j >= nfull);
        int jb = j * 64;
        #pragma unroll
        for (int nt = 0; nt < 8; ++nt) {
            #pragma unroll
            for (int c = 0; c < 4; ++c) {
                float val = sacc[nt][c] * 0.125f;
                if (masked) {
                    int col = jb + 8 * nt + 2 * t + (c & 1);
                    int row = rowg0 + ((c >> 1) << 3);
                    if (col > row) val = -1e30f;
                }
                sacc[nt][c] = val;
            }
        }

        float m0 = -1e30f, m1 = -1e30f;
        #pragma unroll
        for (int nt = 0; nt < 8; ++nt) {
            m0 = fmaxf(m0, fmaxf(sacc[nt][0], sacc[nt][1]));
            m1 = fmaxf(m1, fmaxf(sacc[nt][2], sacc[nt][3]));
        }
        m0 = fmaxf(m0, __shfl_xor_sync(0xffffffffu, m0, 1));
        m0 = fmaxf(m0, __shfl_xor_sync(0xffffffffu, m0, 2));
        m1 = fmaxf(m1, __shfl_xor_sync(0xffffffffu, m1, 1));
        m1 = fmaxf(m1, __shfl_xor_sync(0xffffffffu, m1, 2));
        float mn0 = fmaxf(mrow0, m0);
        float mn1 = fmaxf(mrow1, m1);
        float corr0 = __expf(mrow0 - mn0);
        float corr1 = __expf(mrow1 - mn1);
        mrow0 = mn0; mrow1 = mn1;

        unsigned ph01[8], ph23[8];
        float rs0 = 0.0f, rs1 = 0.0f;
        #pragma unroll
        for (int nt = 0; nt < 8; ++nt) {
            float p0 = __expf(sacc[nt][0] - mn0);
            float p1 = __expf(sacc[nt][1] - mn0);
            float p2 = __expf(sacc[nt][2] - mn1);
            float p3 = __expf(sacc[nt][3] - mn1);
            rs0 += p0 + p1;
            rs1 += p2 + p3;
            ph01[nt] = packh2(p0, p1);
            ph23[nt] = packh2(p2, p3);
        }
        rs0 += __shfl_xor_sync(0xffffffffu, rs0, 1);
        rs0 += __shfl_xor_sync(0xffffffffu, rs0, 2);
        rs1 += __shfl_xor_sync(0xffffffffu, rs1, 1);
        rs1 += __shfl_xor_sync(0xffffffffu, rs1, 2);
        lrow0 = lrow0 * corr0 + rs0;
        lrow1 = lrow1 * corr1 + rs1;
        #pragma unroll
        for (int nd = 0; nd < 8; ++nd) {
            oacc[nd][0] *= corr0; oacc[nd][1] *= corr0;
            oacc[nd][2] *= corr1; oacc[nd][3] *= corr1;
        }

        #pragma unroll
        for (int kc = 0; kc < 4; ++kc) {
            unsigned pa[4] = { ph01[2 * kc], ph23[2 * kc],
                               ph01[2 * kc + 1], ph23[2 * kc + 1] };
            #pragma unroll
            for (int nd2 = 0; nd2 < 4; ++nd2) {
                int lr = 16 * kc + (lane & 15);
                int lc = (2 * nd2 + (lane >> 4)) ^ (lr & 7);
                unsigned bv[4];
                ldmx4t(bv, uVb + lr * 128 + lc * 16);
                mma16h(oacc[2 * nd2],     pa, bv);
                mma16h(oacc[2 * nd2 + 1], pa, bv + 2);
            }
        }

        if (j + 1 < ntiles) cp_wait0();
        __syncthreads();
    }
    #undef STAGEKV

    float inv0 = 1.0f / lrow0;
    float inv1 = 1.0f / lrow1;
    #pragma unroll
    for (int nd = 0; nd < 8; ++nd) {
        int col = 8 * nd + 2 * t;
        size_t off0 = obase + (size_t)(rowg0) * DM + col;
        size_t off1 = obase + (size_t)(rowg0 + 8) * DM + col;
        *(__half2*)(ao + off0) = __floats2half2_rn(oacc[nd][0] * inv0,
                                                   oacc[nd][1] * inv0);
        *(__half2*)(ao + off1) = __floats2half2_rn(oacc[nd][2] * inv1,
                                                   oacc[nd][3] * inv1);
    }
}

// ---------------------------------------------------------------------------
// Launch
// ---------------------------------------------------------------------------
extern "C" void kernel_launch(void* const* d_in, const int* in_sizes, int n_in,
                              void* d_out, int out_size) {
    const float* x     = (const float*)d_in[0];
    const float* wq    = (const float*)d_in[1];
    const float* wk    = (const float*)d_in[2];
    const float* wv    = (const float*)d_in[3];
    const float* wo    = (const float*)d_in[4];
    const float* ln1w  = (const float*)d_in[5];
    const float* ln2w  = (const float*)d_in[6];
    const float* upw   = (const float*)d_in[7];
    const float* gatew = (const float*)d_in[8];
    const float* downw = (const float*)d_in[9];
    float* out = (float*)d_out;

    float *x1, *gate;
    cudaGetSymbolAddress((void**)&x1,   g_x1);
    cudaGetSymbolAddress((void**)&gate, g_gate);

    f16 *qkv16, *xn16, *ao16, *h16;
    f16 *wqkv16, *wo16, *up16, *gw16, *dw16;
    cudaGetSymbolAddress((void**)&qkv16,  g_qkv16);
    cudaGetSymbolAddress((void**)&xn16,   g_xn16);
    cudaGetSymbolAddress((void**)&ao16,   g_ao16);
    cudaGetSymbolAddress((void**)&h16,    g_h16);
    cudaGetSymbolAddress((void**)&wqkv16, g_wqkv16);
    cudaGetSymbolAddress((void**)&wo16,   g_wo16);
    cudaGetSymbolAddress((void**)&up16,   g_up16);
    cudaGetSymbolAddress((void**)&gw16,   g_gw16);
    cudaGetSymbolAddress((void**)&dw16,   g_dw16);

    cudaFuncSetAttribute(flash_kernel,
                         cudaFuncAttributeMaxDynamicSharedMemorySize, 49152);
    cudaFuncSetAttribute(hgemm_kernel<0>,
                         cudaFuncAttributeMaxDynamicSharedMemorySize, 49152);
    cudaFuncSetAttribute(hgemm_kernel<1>,
                         cudaFuncAttributeMaxDynamicSharedMemorySize, 49152);
    cudaFuncSetAttribute(hgemm_kernel<2>,
                         cudaFuncAttributeMaxDynamicSharedMemorySize, 49152);
    cudaFuncSetAttribute(hgemm_kernel<3>,
                         cudaFuncAttributeMaxDynamicSharedMemorySize, 49152);

    dim3 g1(DM / 128, M_ROWS / 128);    // (8, 64)
    dim3 gqkv(QLD / 128, M_ROWS / 128); // (24, 64)
    dim3 g2(DFF / 128, M_ROWS / 128);   // (32, 64)

    // Weight conversions (q,k,v concatenated)
    cvt16_kernel<<<DM * DM / 1024, 256>>>(wq, wqkv16);
    cvt16_kernel<<<DM * DM / 1024, 256>>>(wk, wqkv16 + DM * DM);
    cvt16_kernel<<<DM * DM / 1024, 256>>>(wv, wqkv16 + 2 * DM * DM);
    cvt16_kernel<<<DM * DM / 1024, 256>>>(wo, wo16);
    cvt16_kernel<<<DFF * DM / 1024, 256>>>(upw, up16);
    cvt16_kernel<<<DFF * DM / 1024, 256>>>(gatew, gw16);
    cvt16_kernel<<<DM * DFF / 1024, 256>>>(downw, dw16);

    // ln1 -> fp16 xn
    rmsnorm16_kernel<<<M_ROWS, 256>>>(x, ln1w, xn16);
    // fused qkv projection -> fp16 [M, 3072]
    hgemm_kernel<3><<<gqkv, 256, 49152>>>(xn16, wqkv16, nullptr, qkv16, nullptr, QLD, DM);
    rope16_kernel<<<(M_ROWS * 512) / 256, 256>>>(qkv16);
    // fp16 flash attention
    flash_kernel<<<dim3(SEQ / 128, B_SZ * NHEAD), 256, 49152>>>(qkv16, ao16);
    // o projection + residual
    hgemm_kernel<1><<<g1, 256, 49152>>>(ao16, wo16, x1, nullptr, x, DM, DM);
    // ln2 -> fp16 xn
    rmsnorm16_kernel<<<M_ROWS, 256>>>(x1, ln2w, xn16);
    // FFN
    hgemm_kernel<0><<<g2, 256, 49152>>>(xn16, gw16, gate, nullptr, nullptr, DFF, DM);
    hgemm_kernel<2><<<g2, 256, 49152>>>(xn16, up16, nullptr, h16, gate, DFF, DM);
    hgemm_kernel<1><<<g1, 256, 49152>>>(h16, dw16, out, nullptr, x1, DM, DFF);
}

// round 17
// speedup vs baseline: 2.9216x; 1.0120x over previous
#include <cuda_runtime.h>
#include <cuda_fp16.h>
#include <math.h>
#include <stdint.h>

// Problem constants
#define B_SZ 4
#define SEQ 2048
#define DM 1024
#define NHEAD 16
#define HD 64
#define DFF 4096
#define M_ROWS (B_SZ * SEQ)   // 8192
#define QLD 3072              // fused qkv row stride

typedef __half f16;

// ---------------------------------------------------------------------------
// Scratch buffers
// ---------------------------------------------------------------------------
__device__ float g_x1[M_ROWS * DM];
__device__ float g_gate[M_ROWS * DFF];

__device__ f16 g_qkv16[M_ROWS * QLD];
__device__ f16 g_xn16[M_ROWS * DM];
__device__ f16 g_ao16[M_ROWS * DM];
__device__ f16 g_h16[M_ROWS * DFF];

__device__ f16 g_wqkv16[3 * DM * DM];
__device__ f16 g_wo16[DM * DM];
__device__ f16 g_up16[DFF * DM];
__device__ f16 g_gw16[DFF * DM];
__device__ f16 g_dw16[DM * DFF];

__device__ __forceinline__ unsigned packh2(float a, float b) {
    __half2 h = __floats2half2_rn(a, b);
    return *(unsigned*)&h;
}

// ---------------------------------------------------------------------------
// Elementwise kernels
// ---------------------------------------------------------------------------
__global__ __launch_bounds__(256)
void cvt16_kernel(const float* __restrict__ src, f16* __restrict__ dst) {
    size_t i = ((size_t)blockIdx.x * 256 + threadIdx.x) * 4;
    float4 v = *(const float4*)(src + i);
    *(__half2*)(dst + i)     = __floats2half2_rn(v.x, v.y);
    *(__half2*)(dst + i + 2) = __floats2half2_rn(v.z, v.w);
}

__global__ __launch_bounds__(256)
void rmsnorm16_kernel(const float* __restrict__ x,
                      const float* __restrict__ w,
                      f16* __restrict__ y) {
    int row = blockIdx.x;
    int tid = threadIdx.x;
    const float* xr = x + (size_t)row * DM;
    float4 v = *(const float4*)(xr + tid * 4);
    float s = v.x * v.x + v.y * v.y + v.z * v.z + v.w * v.w;
    #pragma unroll
    for (int off = 16; off; off >>= 1)
        s += __shfl_xor_sync(0xffffffffu, s, off);
    __shared__ float red[8];
    if ((tid & 31) == 0) red[tid >> 5] = s;
    __syncthreads();
    float tot = red[0] + red[1] + red[2] + red[3] +
                red[4] + red[5] + red[6] + red[7];
    float inv = rsqrtf(tot * (1.0f / DM) + 1e-5f);
    float4 wv = *(const float4*)(w + tid * 4);
    size_t o = (size_t)row * DM + tid * 4;
    *(__half2*)(y + o)     = __floats2half2_rn(v.x * inv * wv.x,
                                               v.y * inv * wv.y);
    *(__half2*)(y + o + 2) = __floats2half2_rn(v.z * inv * wv.z,
                                               v.w * inv * wv.w);
}

// ---------------------------------------------------------------------------
// mma / ldmatrix / cp.async primitives
// ---------------------------------------------------------------------------
__device__ __forceinline__ void mma16h(float* d, const unsigned* a,
                                       const unsigned* b) {
    asm volatile(
        "mma.sync.aligned.m16n8k16.row.col.f32.f16.f16.f32 "
        "{%0,%1,%2,%3}, {%4,%5,%6,%7}, {%8,%9}, {%0,%1,%2,%3};"
        : "+f"(d[0]), "+f"(d[1]), "+f"(d[2]), "+f"(d[3])
        : "r"(a[0]), "r"(a[1]), "r"(a[2]), "r"(a[3]), "r"(b[0]), "r"(b[1]));
}
__device__ __forceinline__ void ldmx4(unsigned* r, uint32_t addr) {
    asm volatile(
        "ldmatrix.sync.aligned.m8n8.x4.shared.b16 {%0,%1,%2,%3}, [%4];"
        : "=r"(r[0]), "=r"(r[1]), "=r"(r[2]), "=r"(r[3]) : "r"(addr));
}
__device__ __forceinline__ void ldmx4t(unsigned* r, uint32_t addr) {
    asm volatile(
        "ldmatrix.sync.aligned.m8n8.x4.trans.shared.b16 {%0,%1,%2,%3}, [%4];"
        : "=r"(r[0]), "=r"(r[1]), "=r"(r[2]), "=r"(r[3]) : "r"(addr));
}
__device__ __forceinline__ void cp_async16(uint32_t s, const void* g) {
    asm volatile("cp.async.cg.shared.global [%0], [%1], 16;\n"
                 :: "r"(s), "l"(g));
}
__device__ __forceinline__ void cp_commit() {
    asm volatile("cp.async.commit_group;\n");
}
__device__ __forceinline__ void cp_wait0() {
    asm volatile("cp.async.wait_group 0;\n");
}
__device__ __forceinline__ void cp_wait1() {
    asm volatile("cp.async.wait_group 1;\n");
}

// ---------------------------------------------------------------------------
// fp16 1-term GEMM, 3-stage cp.async pipeline, 2 CTAs/SM.
// EPI: 0 C=AB(fp32); 1 C=AB+aux(fp32); 2 C16=half(silu(AB)*aux);
//      3 C16=half(AB); 4 C16=half(rope(AB)) for qkv (rope cols < 2048)
// ---------------------------------------------------------------------------
template <int EPI>
__global__ __launch_bounds__(256, 2)
void hgemm_kernel(const f16* __restrict__ A, const f16* __restrict__ W,
                  float* __restrict__ C, f16* __restrict__ C16,
                  const float* __restrict__ aux, int N, int K) {
    extern __shared__ char smc[];
    int tid = threadIdx.x;
    int wid = tid >> 5, lane = tid & 31;
    int g = lane >> 2, t = lane & 3;
    int wm = wid >> 2, wn = wid & 3;
    int m0 = blockIdx.y * 128;
    int n0 = blockIdx.x * 128;

    uint32_t smem_base = (uint32_t)__cvta_generic_to_shared(smc);

    int mm = lane >> 3;
    int aRowLoc = (mm & 1) * 8 + (lane & 7);
    int aCb = mm >> 1;
    int bRowLoc = (mm >> 1) * 8 + (lane & 7);
    int bCb = mm & 1;

    uint32_t aOff[4]; int aSw[4];
    #pragma unroll
    for (int mt = 0; mt < 4; ++mt) {
        int r = wm * 64 + mt * 16 + aRowLoc;
        aOff[mt] = r * 64;
        aSw[mt] = (r >> 1) & 3;
    }
    uint32_t bOff[2]; int bSw[2];
    #pragma unroll
    for (int nt2 = 0; nt2 < 2; ++nt2) {
        int r = wn * 32 + nt2 * 16 + bRowLoc;
        bOff[nt2] = r * 64;
        bSw[nt2] = (r >> 1) & 3;
    }

    float acc[4][4][4];
    #pragma unroll
    for (int i = 0; i < 4; ++i)
        #pragma unroll
        for (int j = 0; j < 4; ++j)
            #pragma unroll
            for (int c = 0; c < 4; ++c) acc[i][j][c] = 0.0f;

    int niter = K >> 5;
    int grow = tid >> 1;
    int gch0 = (tid & 1) << 1;

    #define STAGE(buf, k0)                                                      \
    {                                                                           \
        _Pragma("unroll")                                                       \
        for (int cc = 0; cc < 2; ++cc) {                                        \
            int ch = gch0 + cc;                                                 \
            uint32_t soff = (uint32_t)(grow * 64 +                              \
                ((ch ^ ((grow >> 1) & 3)) << 4));                               \
            size_t ga = (size_t)(m0 + grow) * K + (k0) + ch * 8;                \
            size_t gb = (size_t)(n0 + grow) * K + (k0) + ch * 8;                \
            uint32_t sb = smem_base + (buf) * 16384 + soff;                     \
            cp_async16(sb,        A + ga);                                      \
            cp_async16(sb + 8192, W + gb);                                      \
        }                                                                       \
        cp_commit();                                                            \
    }

    STAGE(0, 0);
    STAGE(1, 32);

    int buf = 0;
    for (int it = 0; it < niter; ++it) {
        if (it == niter - 1) cp_wait0(); else cp_wait1();
        __syncthreads();
        if (it + 2 < niter) {
            int nb = buf + 2; if (nb >= 3) nb -= 3;
            STAGE(nb, (it + 2) << 5);
        }

        uint32_t tA = smem_base + buf * 16384;
        uint32_t tB = tA + 8192;

        #pragma unroll
        for (int ck = 0; ck < 2; ++ck) {
            unsigned bf[2][4];
            #pragma unroll
            for (int nt2 = 0; nt2 < 2; ++nt2) {
                uint32_t off = bOff[nt2] +
                               (((2 * ck + bCb) ^ bSw[nt2]) << 4);
                ldmx4(bf[nt2], tB + off);
            }
            #pragma unroll
            for (int mp = 0; mp < 2; ++mp) {
                int mt0 = 2 * mp, mt1 = 2 * mp + 1;
                uint32_t off0 = aOff[mt0] + (((2 * ck + aCb) ^ aSw[mt0]) << 4);
                uint32_t off1 = aOff[mt1] + (((2 * ck + aCb) ^ aSw[mt1]) << 4);
                unsigned a0[4], a1[4];
                ldmx4(a0, tA + off0);
                ldmx4(a1, tA + off1);
                mma16h(acc[mt0][0], a0, bf[0]);
                mma16h(acc[mt0][1], a0, bf[0] + 2);
                mma16h(acc[mt0][2], a0, bf[1]);
                mma16h(acc[mt0][3], a0, bf[1] + 2);
                mma16h(acc[mt1][0], a1, bf[0]);
                mma16h(acc[mt1][1], a1, bf[0] + 2);
                mma16h(acc[mt1][2], a1, bf[1]);
                mma16h(acc[mt1][3], a1, bf[1] + 2);
            }
        }

        if (++buf == 3) buf = 0;
    }
    #undef STAGE

    #pragma unroll
    for (int mt = 0; mt < 4; ++mt) {
        #pragma unroll
        for (int nt = 0; nt < 4; ++nt) {
            int rb = m0 + wm * 64 + mt * 16 + g;
            int cb = n0 + wn * 32 + nt * 8 + 2 * t;
            #pragma unroll
            for (int half = 0; half < 2; ++half) {
                int row = rb + half * 8;
                size_t off = (size_t)row * N + cb;
                float u0 = acc[mt][nt][half * 2];
                float u1 = acc[mt][nt][half * 2 + 1];
                if (EPI == 0) {
                    C[off] = u0; C[off + 1] = u1;
                } else if (EPI == 1) {
                    C[off] = u0 + aux[off];
                    C[off + 1] = u1 + aux[off + 1];
                } else if (EPI == 2) {
                    float s0 = 1.0f / (1.0f + __expf(-u0));
                    float s1 = 1.0f / (1.0f + __expf(-u1));
                    *(__half2*)(C16 + off) =
                        __floats2half2_rn(u0 * s0 * aux[off],
                                          u1 * s1 * aux[off + 1]);
                } else if (EPI == 3) {
                    *(__half2*)(C16 + off) = __floats2half2_rn(u0, u1);
                } else {
                    // EPI 4: fused RoPE for q (cols 0..1023) and k (1024..2047)
                    if (cb < 2048) {
                        int s = row & (SEQ - 1);
                        int pp = (cb & 63) >> 1;
                        float inv_freq =
                            __expf(-(float)(2 * pp) *
                                   (9.210340371976184f / 64.0f));
                        float ang = (float)s * inv_freq;
                        float sn, cs;
                        __sincosf(ang, &sn, &cs);
                        float r0 = u0 * cs - u1 * sn;
                        float r1 = u1 * cs + u0 * sn;
                        *(__half2*)(C16 + off) = __floats2half2_rn(r0, r1);
                    } else {
                        *(__half2*)(C16 + off) = __floats2half2_rn(u0, u1);
                    }
                }
            }
        }
    }
}

// ---------------------------------------------------------------------------
// fp16 flash attention (causal) over fused qkv buffer (stride QLD).
// smem: Q 16K | K[2] 8K each | V[2] 8K each = 48KB. 2 CTAs/SM.
// ---------------------------------------------------------------------------
__global__ __launch_bounds__(256, 2)
void flash_kernel(const f16* __restrict__ qkv, f16* __restrict__ ao) {
    extern __shared__ char sm[];
    uint32_t uQ = (uint32_t)__cvta_generic_to_shared(sm);
    uint32_t uK = uQ + 16384;
    uint32_t uV = uQ + 32768;

    int tid = threadIdx.x;
    int wid = tid >> 5, lane = tid & 31;
    int g = lane >> 2, t = lane & 3;
    int qb = blockIdx.x;
    int bh = blockIdx.y;
    int b = bh >> 4, h = bh & 15;
    int i0 = qb * 128;
    size_t base  = ((size_t)b * SEQ) * QLD + h * HD;   // q; k=+1024, v=+2048
    size_t obase = ((size_t)b * SEQ) * DM + h * HD;

    int ntiles = 2 * qb + 2;
    int nfull  = 2 * qb;

    #define STAGEKV(j, bufv)                                                   \
    {                                                                          \
        int row = tid >> 2;                                                    \
        int ch0 = (tid & 3) * 2;                                               \
        const f16* kg = qkv + base + 1024 +                                    \
                        (size_t)((j) * 64 + row) * QLD + ch0 * 8;              \
        const f16* vg = qkv + base + 2048 +                                    \
                        (size_t)((j) * 64 + row) * QLD + ch0 * 8;              \
        _Pragma("unroll")                                                      \
        for (int cc = 0; cc < 2; ++cc) {                                       \
            int ch = ch0 + cc;                                                 \
            uint32_t so = (uint32_t)(row * 128 + ((ch ^ (row & 7)) << 4));     \
            cp_async16(uK + (bufv) * 8192 + so, kg + cc * 8);                  \
            cp_async16(uV + (bufv) * 8192 + so, vg + cc * 8);                  \
        }                                                                      \
        cp_commit();                                                           \
    }

    {
        int row = tid >> 1;
        int ch0 = (tid & 1) * 4;
        const f16* qg = qkv + base + (size_t)(i0 + row) * QLD + ch0 * 8;
        #pragma unroll
        for (int cc = 0; cc < 4; ++cc) {
            int ch = ch0 + cc;
            uint32_t so = (uint32_t)(row * 128 + ((ch ^ (row & 7)) << 4));
            cp_async16(uQ + so, qg + cc * 8);
        }
        cp_commit();
    }
    STAGEKV(0, 0);
    cp_wait0();
    __syncthreads();

    int r0 = 16 * wid;
    unsigned aq[4][4];
    #pragma unroll
    for (int kc = 0; kc < 4; ++kc) {
        int m = lane >> 3;
        int lr = r0 + (lane & 7) + (m & 1) * 8;
        int lc = (2 * kc + (m >> 1)) ^ (lr & 7);
        ldmx4(aq[kc], uQ + lr * 128 + lc * 16);
    }

    float oacc[8][4];
    #pragma unroll
    for (int i = 0; i < 8; ++i)
        #pragma unroll
        for (int c = 0; c < 4; ++c) oacc[i][c] = 0.0f;
    float mrow0 = -1e30f, mrow1 = -1e30f;
    float lrow0 = 0.0f, lrow1 = 0.0f;
    int rowg0 = i0 + r0 + g;

    for (int j = 0; j < ntiles; ++j) {
        int buf = j & 1;
        if (j + 1 < ntiles) STAGEKV(j + 1, buf ^ 1);
        uint32_t uKb = uK + buf * 8192;
        uint32_t uVb = uV + buf * 8192;

        float sacc[8][4];
        #pragma unroll
        for (int i = 0; i < 8; ++i)
            #pragma unroll
            for (int c = 0; c < 4; ++c) sacc[i][c] = 0.0f;

        #pragma unroll
        for (int nt = 0; nt < 8; ++nt) {
            #pragma unroll
            for (int p = 0; p < 2; ++p) {
                int lr = 8 * nt + (lane & 7);
                int lc = (4 * p + (lane >> 3)) ^ (lr & 7);
                unsigned bk[4];
                ldmx4(bk, uKb + lr * 128 + lc * 16);
                mma16h(sacc[nt], aq[2 * p],     bk);
                mma16h(sacc[nt], aq[2 * p + 1], bk + 2);
            }
        }

        bool masked = (j >= nfull);
        int jb = j * 64;
        #pragma unroll
        for (int nt = 0; nt < 8; ++nt) {
            #pragma unroll
            for (int c = 0; c < 4; ++c) {
                float val = sacc[nt][c] * 0.125f;
                if (masked) {
                    int col = jb + 8 * nt + 2 * t + (c & 1);
                    int row = rowg0 + ((c >> 1) << 3);
                    if (col > row) val = -1e30f;
                }
                sacc[nt][c] = val;
            }
        }

        float m0 = -1e30f, m1 = -1e30f;
        #pragma unroll
        for (int nt = 0; nt < 8; ++nt) {
            m0 = fmaxf(m0, fmaxf(sacc[nt][0], sacc[nt][1]));
            m1 = fmaxf(m1, fmaxf(sacc[nt][2], sacc[nt][3]));
        }
        m0 = fmaxf(m0, __shfl_xor_sync(0xffffffffu, m0, 1));
        m0 = fmaxf(m0, __shfl_xor_sync(0xffffffffu, m0, 2));
        m1 = fmaxf(m1, __shfl_xor_sync(0xffffffffu, m1, 1));
        m1 = fmaxf(m1, __shfl_xor_sync(0xffffffffu, m1, 2));
        float mn0 = fmaxf(mrow0, m0);
        float mn1 = fmaxf(mrow1, m1);
        float corr0 = __expf(mrow0 - mn0);
        float corr1 = __expf(mrow1 - mn1);
        mrow0 = mn0; mrow1 = mn1;

        unsigned ph01[8], ph23[8];
        float rs0 = 0.0f, rs1 = 0.0f;
        #pragma unroll
        for (int nt = 0; nt < 8; ++nt) {
            float p0 = __expf(sacc[nt][0] - mn0);
            float p1 = __expf(sacc[nt][1] - mn0);
            float p2 = __expf(sacc[nt][2] - mn1);
            float p3 = __expf(sacc[nt][3] - mn1);
            rs0 += p0 + p1;
            rs1 += p2 + p3;
            ph01[nt] = packh2(p0, p1);
            ph23[nt] = packh2(p2, p3);
        }
        rs0 += __shfl_xor_sync(0xffffffffu, rs0, 1);
        rs0 += __shfl_xor_sync(0xffffffffu, rs0, 2);
        rs1 += __shfl_xor_sync(0xffffffffu, rs1, 1);
        rs1 += __shfl_xor_sync(0xffffffffu, rs1, 2);
        lrow0 = lrow0 * corr0 + rs0;
        lrow1 = lrow1 * corr1 + rs1;
        #pragma unroll
        for (int nd = 0; nd < 8; ++nd) {
            oacc[nd][0] *= corr0; oacc[nd][1] *= corr0;
            oacc[nd][2] *= corr1; oacc[nd][3] *= corr1;
        }

        #pragma unroll
        for (int kc = 0; kc < 4; ++kc) {
            unsigned pa[4] = { ph01[2 * kc], ph23[2 * kc],
                               ph01[2 * kc + 1], ph23[2 * kc + 1] };
            #pragma unroll
            for (int nd2 = 0; nd2 < 4; ++nd2) {
                int lr = 16 * kc + (lane & 15);
                int lc = (2 * nd2 + (lane >> 4)) ^ (lr & 7);
                unsigned bv[4];
                ldmx4t(bv, uVb + lr * 128 + lc * 16);
                mma16h(oacc[2 * nd2],     pa, bv);
                mma16h(oacc[2 * nd2 + 1], pa, bv + 2);
            }
        }

        if (j + 1 < ntiles) cp_wait0();
        __syncthreads();
    }
    #undef STAGEKV

    float inv0 = 1.0f / lrow0;
    float inv1 = 1.0f / lrow1;
    #pragma unroll
    for (int nd = 0; nd < 8; ++nd) {
        int col = 8 * nd + 2 * t;
        size_t off0 = obase + (size_t)(rowg0) * DM + col;
        size_t off1 = obase + (size_t)(rowg0 + 8) * DM + col;
        *(__half2*)(ao + off0) = __floats2half2_rn(oacc[nd][0] * inv0,
                                                   oacc[nd][1] * inv0);
        *(__half2*)(ao + off1) = __floats2half2_rn(oacc[nd][2] * inv1,
                                                   oacc[nd][3] * inv1);
    }
}

// ---------------------------------------------------------------------------
// Launch
// ---------------------------------------------------------------------------
extern "C" void kernel_launch(void* const* d_in, const int* in_sizes, int n_in,
                              void* d_out, int out_size) {
    const float* x     = (const float*)d_in[0];
    const float* wq    = (const float*)d_in[1];
    const float* wk    = (const float*)d_in[2];
    const float* wv    = (const float*)d_in[3];
    const float* wo    = (const float*)d_in[4];
    const float* ln1w  = (const float*)d_in[5];
    const float* ln2w  = (const float*)d_in[6];
    const float* upw   = (const float*)d_in[7];
    const float* gatew = (const float*)d_in[8];
    const float* downw = (const float*)d_in[9];
    float* out = (float*)d_out;

    float *x1, *gate;
    cudaGetSymbolAddress((void**)&x1,   g_x1);
    cudaGetSymbolAddress((void**)&gate, g_gate);

    f16 *qkv16, *xn16, *ao16, *h16;
    f16 *wqkv16, *wo16, *up16, *gw16, *dw16;
    cudaGetSymbolAddress((void**)&qkv16,  g_qkv16);
    cudaGetSymbolAddress((void**)&xn16,   g_xn16);
    cudaGetSymbolAddress((void**)&ao16,   g_ao16);
    cudaGetSymbolAddress((void**)&h16,    g_h16);
    cudaGetSymbolAddress((void**)&wqkv16, g_wqkv16);
    cudaGetSymbolAddress((void**)&wo16,   g_wo16);
    cudaGetSymbolAddress((void**)&up16,   g_up16);
    cudaGetSymbolAddress((void**)&gw16,   g_gw16);
    cudaGetSymbolAddress((void**)&dw16,   g_dw16);

    cudaFuncSetAttribute(flash_kernel,
                         cudaFuncAttributeMaxDynamicSharedMemorySize, 49152);
    cudaFuncSetAttribute(hgemm_kernel<0>,
                         cudaFuncAttributeMaxDynamicSharedMemorySize, 49152);
    cudaFuncSetAttribute(hgemm_kernel<1>,
                         cudaFuncAttributeMaxDynamicSharedMemorySize, 49152);
    cudaFuncSetAttribute(hgemm_kernel<2>,
                         cudaFuncAttributeMaxDynamicSharedMemorySize, 49152);
    cudaFuncSetAttribute(hgemm_kernel<3>,
                         cudaFuncAttributeMaxDynamicSharedMemorySize, 49152);
    cudaFuncSetAttribute(hgemm_kernel<4>,
                         cudaFuncAttributeMaxDynamicSharedMemorySize, 49152);

    dim3 g1(DM / 128, M_ROWS / 128);    // (8, 64)
    dim3 gqkv(QLD / 128, M_ROWS / 128); // (24, 64)
    dim3 g2(DFF / 128, M_ROWS / 128);   // (32, 64)

    // Weight conversions (q,k,v concatenated)
    cvt16_kernel<<<DM * DM / 1024, 256>>>(wq, wqkv16);
    cvt16_kernel<<<DM * DM / 1024, 256>>>(wk, wqkv16 + DM * DM);
    cvt16_kernel<<<DM * DM / 1024, 256>>>(wv, wqkv16 + 2 * DM * DM);
    cvt16_kernel<<<DM * DM / 1024, 256>>>(wo, wo16);
    cvt16_kernel<<<DFF * DM / 1024, 256>>>(upw, up16);
    cvt16_kernel<<<DFF * DM / 1024, 256>>>(gatew, gw16);
    cvt16_kernel<<<DM * DFF / 1024, 256>>>(downw, dw16);

    // ln1 -> fp16 xn
    rmsnorm16_kernel<<<M_ROWS, 256>>>(x, ln1w, xn16);
    // fused qkv projection + RoPE -> fp16 [M, 3072]
    hgemm_kernel<4><<<gqkv, 256, 49152>>>(xn16, wqkv16, nullptr, qkv16, nullptr, QLD, DM);
    // fp16 flash attention
    flash_kernel<<<dim3(SEQ / 128, B_SZ * NHEAD), 256, 49152>>>(qkv16, ao16);
    // o projection + residual
    hgemm_kernel<1><<<g1, 256, 49152>>>(ao16, wo16, x1, nullptr, x, DM, DM);
    // ln2 -> fp16 xn
    rmsnorm16_kernel<<<M_ROWS, 256>>>(x1, ln2w, xn16);
    // FFN
    hgemm_kernel<0><<<g2, 256, 49152>>>(xn16, gw16, gate, nullptr, nullptr, DFF, DM);
    hgemm_kernel<2><<<g2, 256, 49152>>>(xn16, up16, nullptr, h16, gate, DFF, DM);
    hgemm_kernel<1><<<g1, 256, 49152>>>(h16, dw16, out, nullptr, x1, DM, DFF);
}